// round 4
// baseline (speedup 1.0000x reference)
#include <cuda_runtime.h>
#include <math.h>

#define IN_DIM   256
#define STATE    512
#define OUT_DIM  256
#define NSEQ     32768

// ---------------- device scratch (no allocation allowed), 16B-aligned ----------------
__device__ __align__(16) float g_lam_re[STATE];
__device__ __align__(16) float g_lam_im[STATE];
__device__ __align__(16) float g_gam[STATE];
__device__ __align__(16) float g_G[2 * STATE * IN_DIM];  // [1024,256]: row 2h = Bn_re[h,:], row 2h+1 = Bn_im[h,:]
__device__ __align__(16) float g_P[OUT_DIM * STATE];     // [256,512]
__device__ __align__(16) float g_Q[OUT_DIM * STATE];     // [256,512]
__device__ __align__(16) float g_F[OUT_DIM * IN_DIM];    // [256,256] = D + C_re@Bn_re - C_im@Bn_im

// ---------------- tiny precompute kernels ----------------
__global__ void k_lam(const float* __restrict__ nu_log,
                      const float* __restrict__ theta_log,
                      const float* __restrict__ gamma_log) {
    int h = threadIdx.x;
    float mod = expf(-expf(nu_log[h]));
    float th  = expf(theta_log[h]);
    g_lam_re[h] = mod * cosf(th);
    g_lam_im[h] = mod * sinf(th);
    g_gam[h]    = expf(gamma_log[h]);
}

__global__ void k_weights(const float* __restrict__ B_re, const float* __restrict__ B_im,
                          const float* __restrict__ C_re, const float* __restrict__ C_im) {
    int idx = blockIdx.x * blockDim.x + threadIdx.x;
    const int NG = 2 * STATE * IN_DIM;    // 262144
    const int NP = OUT_DIM * STATE;       // 131072
    if (idx < NG) {
        int c = idx / IN_DIM, j = idx % IN_DIM, h = c >> 1;
        float b = (c & 1) ? B_im[h * IN_DIM + j] : B_re[h * IN_DIM + j];
        g_G[idx] = b * g_gam[h];
    } else if (idx < NG + NP) {
        int t = idx - NG;
        int o = t / STATE, h = t % STATE;
        float cr = C_re[o * STATE + h], ci = C_im[o * STATE + h];
        float lr = g_lam_re[h], li = g_lam_im[h];
        g_P[t] = lr * cr - li * ci;
        g_Q[t] = -(li * cr + lr * ci);
    }
}

// F = D + C_re @ Bn_re - C_im @ Bn_im   (256x256, K=512); Bn rows interleaved in g_G
__global__ void k_F(const float* __restrict__ C_re, const float* __restrict__ C_im,
                    const float* __restrict__ D) {
    __shared__ float sCr[16][16], sCi[16][16], sGr[16][17], sGi[16][17];
    int o0 = blockIdx.y * 16, j0 = blockIdx.x * 16;
    int tx = threadIdx.x, ty = threadIdx.y;
    float acc = 0.f;
    for (int h0 = 0; h0 < STATE; h0 += 16) {
        sCr[ty][tx] = C_re[(o0 + ty) * STATE + h0 + tx];
        sCi[ty][tx] = C_im[(o0 + ty) * STATE + h0 + tx];
        sGr[ty][tx] = g_G[(2 * (h0 + ty)) * IN_DIM + j0 + tx];
        sGi[ty][tx] = g_G[(2 * (h0 + ty) + 1) * IN_DIM + j0 + tx];
        __syncthreads();
#pragma unroll
        for (int k = 0; k < 16; k++)
            acc += sCr[ty][k] * sGr[k][tx] - sCi[ty][k] * sGi[k][tx];
        __syncthreads();
    }
    g_F[(o0 + ty) * IN_DIM + j0 + tx] = D[(o0 + ty) * IN_DIM + j0 + tx] + acc;
}

// ---------------- main GEMM (BM=128, BN=64, BK=16, 256 thr, 8x4 microtile) ----------------
// MODE 0: y = x0_re@P^T + x0_im@Q^T + u@F^T            -> out rows stride 256 (unclamped; validated)
// MODE 1: state interleaved c64: lam*x0 + u@G^T         -> out rows stride 1024, CLAMPED to lim
// MODE 2: state REAL PART only: Re(lam*x0) + u@Gre^T    -> out rows stride 512,  CLAMPED to lim
template <int MODE>
__global__ __launch_bounds__(256)
void k_gemm(const float* __restrict__ A0,
            const float* __restrict__ A1,
            const float* __restrict__ A2,
            int K0, int K1, int K2,
            const float* __restrict__ x0_re,
            const float* __restrict__ x0_im,
            float* __restrict__ out,
            long long lim) {
    const int BM = 128, BN = 64, BK = 16;
    __shared__ float As[BK][BM + 4];
    __shared__ float Bs[BK][BN + 4];

    int tid = threadIdx.x;
    int m0 = blockIdx.x * BM;
    int n0 = blockIdx.y * BN;
    int tx = tid & 15, ty = tid >> 4;

    float acc[8][4];
#pragma unroll
    for (int i = 0; i < 8; i++)
#pragma unroll
        for (int j = 0; j < 4; j++) acc[i][j] = 0.f;

    const float* Aseg[3] = {A0, A1, A2};
    int Kseg[3] = {K0, K1, K2};

#pragma unroll 1
    for (int s = 0; s < 3; s++) {
        int K = Kseg[s];
        if (K == 0) break;
        const float* A = Aseg[s];
        const float* W = (MODE == 0) ? (s == 0 ? g_P : (s == 1 ? g_Q : g_F)) : g_G;

#pragma unroll 1
        for (int k0 = 0; k0 < K; k0 += BK) {
#pragma unroll
            for (int l = 0; l < 2; l++) {
                int f = tid + l * 256;
                int r = f >> 2, kk4 = (f & 3) * 4;
                float4 v = *(const float4*)&A[(size_t)(m0 + r) * K + k0 + kk4];
                As[kk4 + 0][r] = v.x; As[kk4 + 1][r] = v.y;
                As[kk4 + 2][r] = v.z; As[kk4 + 3][r] = v.w;
            }
            {
                int n = tid >> 2, kk4 = (tid & 3) * 4;
                // MODE 2 contracts against Bn_re rows only = even rows of g_G
                int wrow = (MODE == 2) ? 2 * (n0 + n) : (n0 + n);
                float4 v = *(const float4*)&W[(size_t)wrow * K + k0 + kk4];
                Bs[kk4 + 0][n] = v.x; Bs[kk4 + 1][n] = v.y;
                Bs[kk4 + 2][n] = v.z; Bs[kk4 + 3][n] = v.w;
            }
            __syncthreads();

#pragma unroll
            for (int kk = 0; kk < BK; kk++) {
                float4 b  = *(const float4*)&Bs[kk][tx * 4];
                float4 a0 = *(const float4*)&As[kk][ty * 8];
                float4 a1 = *(const float4*)&As[kk][ty * 8 + 4];
                float av[8] = {a0.x, a0.y, a0.z, a0.w, a1.x, a1.y, a1.z, a1.w};
                float bv[4] = {b.x, b.y, b.z, b.w};
#pragma unroll
                for (int i = 0; i < 8; i++)
#pragma unroll
                    for (int j = 0; j < 4; j++) acc[i][j] += av[i] * bv[j];
            }
            __syncthreads();
        }
    }

    if (MODE == 0) {
#pragma unroll
        for (int i = 0; i < 8; i++) {
            int row = m0 + ty * 8 + i;
            float4 v = make_float4(acc[i][0], acc[i][1], acc[i][2], acc[i][3]);
            *(float4*)&out[(size_t)row * OUT_DIM + n0 + tx * 4] = v;
        }
    } else if (MODE == 1) {
        int c0 = n0 + tx * 4;          // even; complex pairs (c0/2, c0/2+1)
        int h0 = c0 >> 1;
        float lr0 = g_lam_re[h0],     li0 = g_lam_im[h0];
        float lr1 = g_lam_re[h0 + 1], li1 = g_lam_im[h0 + 1];
#pragma unroll
        for (int i = 0; i < 8; i++) {
            int row = m0 + ty * 8 + i;
            long long idx = (long long)row * (2 * STATE) + c0;
            if (idx + 3 < lim) {
                float xr0 = x0_re[(size_t)row * STATE + h0];
                float xi0 = x0_im[(size_t)row * STATE + h0];
                float xr1 = x0_re[(size_t)row * STATE + h0 + 1];
                float xi1 = x0_im[(size_t)row * STATE + h0 + 1];
                float4 v;
                v.x = lr0 * xr0 - li0 * xi0 + acc[i][0];
                v.y = lr0 * xi0 + li0 * xr0 + acc[i][1];
                v.z = lr1 * xr1 - li1 * xi1 + acc[i][2];
                v.w = lr1 * xi1 + li1 * xr1 + acc[i][3];
                *(float4*)&out[idx] = v;
            }
        }
    } else {  // MODE 2: real part only, [N, STATE]
        int h0 = n0 + tx * 4;
        float lr[4], li[4];
#pragma unroll
        for (int j = 0; j < 4; j++) { lr[j] = g_lam_re[h0 + j]; li[j] = g_lam_im[h0 + j]; }
#pragma unroll
        for (int i = 0; i < 8; i++) {
            int row = m0 + ty * 8 + i;
            long long idx = (long long)row * STATE + h0;
            if (idx + 3 < lim) {
                float4 v;
                float r[4];
#pragma unroll
                for (int j = 0; j < 4; j++) {
                    float xr = x0_re[(size_t)row * STATE + h0 + j];
                    float xi = x0_im[(size_t)row * STATE + h0 + j];
                    r[j] = lr[j] * xr - li[j] * xi + acc[i][j];
                }
                v.x = r[0]; v.y = r[1]; v.z = r[2]; v.w = r[3];
                *(float4*)&out[idx] = v;
            }
        }
    }
}

// ---------------- launch ----------------
extern "C" void kernel_launch(void* const* d_in, const int* in_sizes, int n_in,
                              void* d_out, int out_size) {
    const long long expect[11] = {
        (long long)NSEQ * IN_DIM,      // u
        (long long)NSEQ * STATE,       // x0_re
        (long long)NSEQ * STATE,       // x0_im
        STATE,                         // nu_log
        STATE,                         // theta_log
        STATE,                         // gamma_log
        (long long)STATE * IN_DIM,     // B_re
        (long long)STATE * IN_DIM,     // B_im
        (long long)OUT_DIM * STATE,    // C_re
        (long long)OUT_DIM * STATE,    // C_im
        (long long)OUT_DIM * IN_DIM    // D
    };
    const float* ptr[11];
    bool used[32] = {false};
    for (int e = 0; e < 11; e++) {
        ptr[e] = nullptr;
        for (int i = 0; i < n_in; i++) {
            if (!used[i] && (long long)in_sizes[i] == expect[e]) {
                ptr[e] = (const float*)d_in[i];
                used[i] = true;
                break;
            }
        }
        if (!ptr[e]) ptr[e] = (const float*)d_in[e < n_in ? e : 0];
    }
    const float* u         = ptr[0];
    const float* x0_re     = ptr[1];
    const float* x0_im     = ptr[2];
    const float* nu_log    = ptr[3];
    const float* theta_log = ptr[4];
    const float* gamma_log = ptr[5];
    const float* B_re      = ptr[6];
    const float* B_im      = ptr[7];
    const float* C_re      = ptr[8];
    const float* C_im      = ptr[9];
    const float* D         = ptr[10];
    float* out = (float*)d_out;

    k_lam<<<1, STATE>>>(nu_log, theta_log, gamma_log);

    int tot = 2 * STATE * IN_DIM + OUT_DIM * STATE;
    k_weights<<<(tot + 255) / 256, 256>>>(B_re, B_im, C_re, C_im);

    k_F<<<dim3(IN_DIM / 16, OUT_DIM / 16), dim3(16, 16)>>>(C_re, C_im, D);

    const long long Y_ELEMS      = (long long)NSEQ * OUT_DIM;   //  8,388,608
    const long long ST_C64_ELEMS = (long long)NSEQ * 2 * STATE; // 33,554,432
    const long long ST_RE_ELEMS  = (long long)NSEQ * STATE;     // 16,777,216

    // Effective float32 capacity of d_out. Known evidence: out_size < 41,943,040
    // (round-2 guard) AND buffer < y+interleaved-state (round-3 OOB crash).
    // If out_size is complex64-counted, capacity is 2x.
    long long cap = (long long)out_size;
    if (cap == Y_ELEMS / 2 + ST_C64_ELEMS / 2) cap *= 2;  // 20,971,520 -> c64-counted

    // y: [N,1280] x [1280,256] — validated (rel 7e-7)
    k_gemm<0><<<dim3(NSEQ / 128, OUT_DIM / 64), 256>>>(
        x0_re, x0_im, u, STATE, STATE, IN_DIM,
        nullptr, nullptr, out, Y_ELEMS);

    float* out_state = out + Y_ELEMS;
    long long rem = cap - Y_ELEMS;
    if (rem >= ST_C64_ELEMS) {
        // full interleaved complex64 state
        k_gemm<1><<<dim3(NSEQ / 128, (2 * STATE) / 64), 256>>>(
            u, nullptr, nullptr, IN_DIM, 0, 0,
            x0_re, x0_im, out_state, rem);
    } else if (rem >= ST_RE_ELEMS) {
        // real-part-only state plane (astype(float32) drops imag)
        k_gemm<2><<<dim3(NSEQ / 128, STATE / 64), 256>>>(
            u, nullptr, nullptr, IN_DIM, 0, 0,
            x0_re, x0_im, out_state, rem);
    }
    // rem < ST_RE_ELEMS: nothing safe to write; y alone (would signal layout mismatch)
}

// round 5
// speedup vs baseline: 1.0053x; 1.0053x over previous
#include <cuda_runtime.h>
#include <math.h>

#define IN_DIM   256
#define STATE    512
#define OUT_DIM  256
#define NSEQ     32768

// ---------------- device scratch (no allocation allowed), 16B-aligned ----------------
__device__ __align__(16) float g_lam_re[STATE];
__device__ __align__(16) float g_lam_im[STATE];
__device__ __align__(16) float g_gam[STATE];
__device__ __align__(16) float g_G[2 * STATE * IN_DIM];  // [1024,256]: row 2h = Bn_re[h,:], row 2h+1 = Bn_im[h,:]
__device__ __align__(16) float g_P[OUT_DIM * STATE];     // [256,512]
__device__ __align__(16) float g_Q[OUT_DIM * STATE];     // [256,512]
__device__ __align__(16) float g_F[OUT_DIM * IN_DIM];    // [256,256] = D + C_re@Bn_re - C_im@Bn_im

// ---------------- tiny precompute kernels ----------------
__global__ void k_lam(const float* __restrict__ nu_log,
                      const float* __restrict__ theta_log,
                      const float* __restrict__ gamma_log) {
    int h = threadIdx.x;
    float mod = expf(-expf(nu_log[h]));
    float th  = expf(theta_log[h]);
    g_lam_re[h] = mod * cosf(th);
    g_lam_im[h] = mod * sinf(th);
    g_gam[h]    = expf(gamma_log[h]);
}

__global__ void k_weights(const float* __restrict__ B_re, const float* __restrict__ B_im,
                          const float* __restrict__ C_re, const float* __restrict__ C_im) {
    int idx = blockIdx.x * blockDim.x + threadIdx.x;
    const int NG = 2 * STATE * IN_DIM;    // 262144
    const int NP = OUT_DIM * STATE;       // 131072
    if (idx < NG) {
        int c = idx / IN_DIM, j = idx % IN_DIM, h = c >> 1;
        float b = (c & 1) ? B_im[h * IN_DIM + j] : B_re[h * IN_DIM + j];
        g_G[idx] = b * g_gam[h];
    } else if (idx < NG + NP) {
        int t = idx - NG;
        int o = t / STATE, h = t % STATE;
        float cr = C_re[o * STATE + h], ci = C_im[o * STATE + h];
        float lr = g_lam_re[h], li = g_lam_im[h];
        g_P[t] = lr * cr - li * ci;
        g_Q[t] = -(li * cr + lr * ci);
    }
}

// F = D + C_re @ Bn_re - C_im @ Bn_im   (256x256, K=512); Bn rows interleaved in g_G
__global__ void k_F(const float* __restrict__ C_re, const float* __restrict__ C_im,
                    const float* __restrict__ D) {
    __shared__ float sCr[16][16], sCi[16][16], sGr[16][17], sGi[16][17];
    int o0 = blockIdx.y * 16, j0 = blockIdx.x * 16;
    int tx = threadIdx.x, ty = threadIdx.y;
    float acc = 0.f;
    for (int h0 = 0; h0 < STATE; h0 += 16) {
        sCr[ty][tx] = C_re[(o0 + ty) * STATE + h0 + tx];
        sCi[ty][tx] = C_im[(o0 + ty) * STATE + h0 + tx];
        sGr[ty][tx] = g_G[(2 * (h0 + ty)) * IN_DIM + j0 + tx];
        sGi[ty][tx] = g_G[(2 * (h0 + ty) + 1) * IN_DIM + j0 + tx];
        __syncthreads();
#pragma unroll
        for (int k = 0; k < 16; k++)
            acc += sCr[ty][k] * sGr[k][tx] - sCi[ty][k] * sGi[k][tx];
        __syncthreads();
    }
    g_F[(o0 + ty) * IN_DIM + j0 + tx] = D[(o0 + ty) * IN_DIM + j0 + tx] + acc;
}

// ---------------- main GEMM (BM=128, BN=64, BK=16, 256 thr, 8x4 microtile) ----------------
// MODE 0: y = x0_re@P^T + x0_im@Q^T + u@F^T            -> out rows stride 256 (unclamped; validated)
// MODE 1: state interleaved c64: lam*x0 + u@G^T         -> out rows stride 1024, CLAMPED to lim
// MODE 2: state REAL PART only: Re(lam*x0) + u@Gre^T    -> out rows stride 512,  CLAMPED to lim
template <int MODE>
__global__ __launch_bounds__(256)
void k_gemm(const float* __restrict__ A0,
            const float* __restrict__ A1,
            const float* __restrict__ A2,
            int K0, int K1, int K2,
            const float* __restrict__ x0_re,
            const float* __restrict__ x0_im,
            float* __restrict__ out,
            long long lim) {
    const int BM = 128, BN = 64, BK = 16;
    __shared__ float As[BK][BM + 4];
    __shared__ float Bs[BK][BN + 4];

    int tid = threadIdx.x;
    int m0 = blockIdx.x * BM;
    int n0 = blockIdx.y * BN;
    int tx = tid & 15, ty = tid >> 4;

    float acc[8][4];
#pragma unroll
    for (int i = 0; i < 8; i++)
#pragma unroll
        for (int j = 0; j < 4; j++) acc[i][j] = 0.f;

    const float* Aseg[3] = {A0, A1, A2};
    int Kseg[3] = {K0, K1, K2};

#pragma unroll 1
    for (int s = 0; s < 3; s++) {
        int K = Kseg[s];
        if (K == 0) break;
        const float* A = Aseg[s];
        const float* W = (MODE == 0) ? (s == 0 ? g_P : (s == 1 ? g_Q : g_F)) : g_G;

#pragma unroll 1
        for (int k0 = 0; k0 < K; k0 += BK) {
#pragma unroll
            for (int l = 0; l < 2; l++) {
                int f = tid + l * 256;
                int r = f >> 2, kk4 = (f & 3) * 4;
                float4 v = *(const float4*)&A[(size_t)(m0 + r) * K + k0 + kk4];
                As[kk4 + 0][r] = v.x; As[kk4 + 1][r] = v.y;
                As[kk4 + 2][r] = v.z; As[kk4 + 3][r] = v.w;
            }
            {
                int n = tid >> 2, kk4 = (tid & 3) * 4;
                // MODE 2 contracts against Bn_re rows only = even rows of g_G
                int wrow = (MODE == 2) ? 2 * (n0 + n) : (n0 + n);
                float4 v = *(const float4*)&W[(size_t)wrow * K + k0 + kk4];
                Bs[kk4 + 0][n] = v.x; Bs[kk4 + 1][n] = v.y;
                Bs[kk4 + 2][n] = v.z; Bs[kk4 + 3][n] = v.w;
            }
            __syncthreads();

#pragma unroll
            for (int kk = 0; kk < BK; kk++) {
                float4 b  = *(const float4*)&Bs[kk][tx * 4];
                float4 a0 = *(const float4*)&As[kk][ty * 8];
                float4 a1 = *(const float4*)&As[kk][ty * 8 + 4];
                float av[8] = {a0.x, a0.y, a0.z, a0.w, a1.x, a1.y, a1.z, a1.w};
                float bv[4] = {b.x, b.y, b.z, b.w};
#pragma unroll
                for (int i = 0; i < 8; i++)
#pragma unroll
                    for (int j = 0; j < 4; j++) acc[i][j] += av[i] * bv[j];
            }
            __syncthreads();
        }
    }

    if (MODE == 0) {
#pragma unroll
        for (int i = 0; i < 8; i++) {
            int row = m0 + ty * 8 + i;
            float4 v = make_float4(acc[i][0], acc[i][1], acc[i][2], acc[i][3]);
            *(float4*)&out[(size_t)row * OUT_DIM + n0 + tx * 4] = v;
        }
    } else if (MODE == 1) {
        int c0 = n0 + tx * 4;          // even; complex pairs (c0/2, c0/2+1)
        int h0 = c0 >> 1;
        float lr0 = g_lam_re[h0],     li0 = g_lam_im[h0];
        float lr1 = g_lam_re[h0 + 1], li1 = g_lam_im[h0 + 1];
#pragma unroll
        for (int i = 0; i < 8; i++) {
            int row = m0 + ty * 8 + i;
            long long idx = (long long)row * (2 * STATE) + c0;
            if (idx + 3 < lim) {
                float xr0 = x0_re[(size_t)row * STATE + h0];
                float xi0 = x0_im[(size_t)row * STATE + h0];
                float xr1 = x0_re[(size_t)row * STATE + h0 + 1];
                float xi1 = x0_im[(size_t)row * STATE + h0 + 1];
                float4 v;
                v.x = lr0 * xr0 - li0 * xi0 + acc[i][0];
                v.y = lr0 * xi0 + li0 * xr0 + acc[i][1];
                v.z = lr1 * xr1 - li1 * xi1 + acc[i][2];
                v.w = lr1 * xi1 + li1 * xr1 + acc[i][3];
                *(float4*)&out[idx] = v;
            }
        }
    } else {  // MODE 2: real part only, [N, STATE]
        int h0 = n0 + tx * 4;
        float lr[4], li[4];
#pragma unroll
        for (int j = 0; j < 4; j++) { lr[j] = g_lam_re[h0 + j]; li[j] = g_lam_im[h0 + j]; }
#pragma unroll
        for (int i = 0; i < 8; i++) {
            int row = m0 + ty * 8 + i;
            long long idx = (long long)row * STATE + h0;
            if (idx + 3 < lim) {
                float4 v;
                float r[4];
#pragma unroll
                for (int j = 0; j < 4; j++) {
                    float xr = x0_re[(size_t)row * STATE + h0 + j];
                    float xi = x0_im[(size_t)row * STATE + h0 + j];
                    r[j] = lr[j] * xr - li[j] * xi + acc[i][j];
                }
                v.x = r[0]; v.y = r[1]; v.z = r[2]; v.w = r[3];
                *(float4*)&out[idx] = v;
            }
        }
    }
}

// ---------------- launch ----------------
extern "C" void kernel_launch(void* const* d_in, const int* in_sizes, int n_in,
                              void* d_out, int out_size) {
    const long long expect[11] = {
        (long long)NSEQ * IN_DIM,      // u
        (long long)NSEQ * STATE,       // x0_re
        (long long)NSEQ * STATE,       // x0_im
        STATE,                         // nu_log
        STATE,                         // theta_log
        STATE,                         // gamma_log
        (long long)STATE * IN_DIM,     // B_re
        (long long)STATE * IN_DIM,     // B_im
        (long long)OUT_DIM * STATE,    // C_re
        (long long)OUT_DIM * STATE,    // C_im
        (long long)OUT_DIM * IN_DIM    // D
    };
    const float* ptr[11];
    bool used[32] = {false};
    for (int e = 0; e < 11; e++) {
        ptr[e] = nullptr;
        for (int i = 0; i < n_in; i++) {
            if (!used[i] && (long long)in_sizes[i] == expect[e]) {
                ptr[e] = (const float*)d_in[i];
                used[i] = true;
                break;
            }
        }
        if (!ptr[e]) ptr[e] = (const float*)d_in[e < n_in ? e : 0];
    }
    const float* u         = ptr[0];
    const float* x0_re     = ptr[1];
    const float* x0_im     = ptr[2];
    const float* nu_log    = ptr[3];
    const float* theta_log = ptr[4];
    const float* gamma_log = ptr[5];
    const float* B_re      = ptr[6];
    const float* B_im      = ptr[7];
    const float* C_re      = ptr[8];
    const float* C_im      = ptr[9];
    const float* D         = ptr[10];
    float* out = (float*)d_out;

    k_lam<<<1, STATE>>>(nu_log, theta_log, gamma_log);

    int tot = 2 * STATE * IN_DIM + OUT_DIM * STATE;
    k_weights<<<(tot + 255) / 256, 256>>>(B_re, B_im, C_re, C_im);

    k_F<<<dim3(IN_DIM / 16, OUT_DIM / 16), dim3(16, 16)>>>(C_re, C_im, D);

    const long long Y_ELEMS      = (long long)NSEQ * OUT_DIM;   //  8,388,608
    const long long ST_C64_ELEMS = (long long)NSEQ * 2 * STATE; // 33,554,432
    const long long ST_RE_ELEMS  = (long long)NSEQ * STATE;     // 16,777,216

    // Effective float32 capacity of d_out. Known evidence: out_size < 41,943,040
    // (round-2 guard) AND buffer < y+interleaved-state (round-3 OOB crash).
    // If out_size is complex64-counted, capacity is 2x.
    long long cap = (long long)out_size;
    if (cap == Y_ELEMS / 2 + ST_C64_ELEMS / 2) cap *= 2;  // 20,971,520 -> c64-counted

    // y: [N,1280] x [1280,256] — validated (rel 7e-7)
    k_gemm<0><<<dim3(NSEQ / 128, OUT_DIM / 64), 256>>>(
        x0_re, x0_im, u, STATE, STATE, IN_DIM,
        nullptr, nullptr, out, Y_ELEMS);

    float* out_state = out + Y_ELEMS;
    long long rem = cap - Y_ELEMS;
    if (rem >= ST_C64_ELEMS) {
        // full interleaved complex64 state
        k_gemm<1><<<dim3(NSEQ / 128, (2 * STATE) / 64), 256>>>(
            u, nullptr, nullptr, IN_DIM, 0, 0,
            x0_re, x0_im, out_state, rem);
    } else if (rem >= ST_RE_ELEMS) {
        // real-part-only state plane (astype(float32) drops imag)
        k_gemm<2><<<dim3(NSEQ / 128, STATE / 64), 256>>>(
            u, nullptr, nullptr, IN_DIM, 0, 0,
            x0_re, x0_im, out_state, rem);
    }
    // rem < ST_RE_ELEMS: nothing safe to write; y alone (would signal layout mismatch)
}

// round 8
// speedup vs baseline: 1.6584x; 1.6496x over previous
#include <cuda_runtime.h>
#include <cuda_bf16.h>
#include <math.h>
#include <stdint.h>

#define IN_DIM   256
#define STATE    512
#define OUT_DIM  256
#define NSEQ     32768
#define KY       1280   // x0_re(512) | x0_im(512) | u(256)

// ---------------- device scratch (no allocation allowed), 16B-aligned ----------------
__device__ __align__(16) float g_lam_re[STATE];
__device__ __align__(16) float g_lam_im[STATE];
__device__ __align__(16) float g_gam[STATE];
__device__ __align__(16) float g_G[2 * STATE * IN_DIM];  // [1024,256] fp32: row 2h = Bn_re[h,:], 2h+1 = Bn_im[h,:]
__device__ __align__(16) float g_P[OUT_DIM * STATE];
__device__ __align__(16) float g_Q[OUT_DIM * STATE];
__device__ __align__(16) float g_F[OUT_DIM * IN_DIM];
// bf16 hi/lo split weights (ONLY referenced from device code — host shadow address is invalid!)
__device__ __align__(16) __nv_bfloat16 g_Wy_hi[OUT_DIM * KY];    // [256][1280] = [P|Q|F] per row
__device__ __align__(16) __nv_bfloat16 g_Wy_lo[OUT_DIM * KY];
__device__ __align__(16) __nv_bfloat16 g_Ws_hi[STATE * IN_DIM];  // [512][256] = Bn_re
__device__ __align__(16) __nv_bfloat16 g_Ws_lo[STATE * IN_DIM];

// ---------------- PTX helpers (all sm_80-era; legal on compute_103) ----------------
__device__ __forceinline__ uint32_t smem_u32(const void* p) {
    uint32_t a;
    asm("{ .reg .u64 t; cvta.to.shared.u64 t, %1; cvt.u32.u64 %0, t; }" : "=r"(a) : "l"(p));
    return a;
}
__device__ __forceinline__ void sts128(uint32_t a, uint32_t x, uint32_t y, uint32_t z, uint32_t w) {
    asm volatile("st.shared.v4.b32 [%0], {%1,%2,%3,%4};" :: "r"(a), "r"(x), "r"(y), "r"(z), "r"(w) : "memory");
}
__device__ __forceinline__ void ldm_x4(uint32_t* r, uint32_t addr) {
    asm volatile("ldmatrix.sync.aligned.m8n8.x4.shared.b16 {%0,%1,%2,%3}, [%4];"
        : "=r"(r[0]), "=r"(r[1]), "=r"(r[2]), "=r"(r[3]) : "r"(addr));
}
__device__ __forceinline__ void ldm_x2(uint32_t* r, uint32_t addr) {
    asm volatile("ldmatrix.sync.aligned.m8n8.x2.shared.b16 {%0,%1}, [%2];"
        : "=r"(r[0]), "=r"(r[1]) : "r"(addr));
}
__device__ __forceinline__ void mma_bf16(float* c, const uint32_t* a, const uint32_t* b) {
    asm volatile(
        "mma.sync.aligned.m16n8k16.row.col.f32.bf16.bf16.f32 "
        "{%0,%1,%2,%3}, {%4,%5,%6,%7}, {%8,%9}, {%0,%1,%2,%3};"
        : "+f"(c[0]), "+f"(c[1]), "+f"(c[2]), "+f"(c[3])
        : "r"(a[0]), "r"(a[1]), "r"(a[2]), "r"(a[3]), "r"(b[0]), "r"(b[1]));
}

// ---------------- tiny precompute kernels ----------------
__global__ void k_lam(const float* __restrict__ nu_log,
                      const float* __restrict__ theta_log,
                      const float* __restrict__ gamma_log) {
    int h = threadIdx.x;
    float mod = expf(-expf(nu_log[h]));
    float th  = expf(theta_log[h]);
    g_lam_re[h] = mod * cosf(th);
    g_lam_im[h] = mod * sinf(th);
    g_gam[h]    = expf(gamma_log[h]);
}

__global__ void k_weights(const float* __restrict__ B_re, const float* __restrict__ B_im,
                          const float* __restrict__ C_re, const float* __restrict__ C_im) {
    int idx = blockIdx.x * blockDim.x + threadIdx.x;
    const int NG = 2 * STATE * IN_DIM;
    const int NP = OUT_DIM * STATE;
    if (idx < NG) {
        int c = idx / IN_DIM, j = idx % IN_DIM, h = c >> 1;
        float b = (c & 1) ? B_im[h * IN_DIM + j] : B_re[h * IN_DIM + j];
        g_G[idx] = b * g_gam[h];
    } else if (idx < NG + NP) {
        int t = idx - NG;
        int o = t / STATE, h = t % STATE;
        float cr = C_re[o * STATE + h], ci = C_im[o * STATE + h];
        float lr = g_lam_re[h], li = g_lam_im[h];
        g_P[t] = lr * cr - li * ci;
        g_Q[t] = -(li * cr + lr * ci);
    }
}

__global__ void k_F(const float* __restrict__ C_re, const float* __restrict__ C_im,
                    const float* __restrict__ D) {
    __shared__ float sCr[16][16], sCi[16][16], sGr[16][17], sGi[16][17];
    int o0 = blockIdx.y * 16, j0 = blockIdx.x * 16;
    int tx = threadIdx.x, ty = threadIdx.y;
    float acc = 0.f;
    for (int h0 = 0; h0 < STATE; h0 += 16) {
        sCr[ty][tx] = C_re[(o0 + ty) * STATE + h0 + tx];
        sCi[ty][tx] = C_im[(o0 + ty) * STATE + h0 + tx];
        sGr[ty][tx] = g_G[(2 * (h0 + ty)) * IN_DIM + j0 + tx];
        sGi[ty][tx] = g_G[(2 * (h0 + ty) + 1) * IN_DIM + j0 + tx];
        __syncthreads();
#pragma unroll
        for (int k = 0; k < 16; k++)
            acc += sCr[ty][k] * sGr[k][tx] - sCi[ty][k] * sGi[k][tx];
        __syncthreads();
    }
    g_F[(o0 + ty) * IN_DIM + j0 + tx] = D[(o0 + ty) * IN_DIM + j0 + tx] + acc;
}

__global__ void k_split() {
    int idx = blockIdx.x * blockDim.x + threadIdx.x;
    const int T1 = OUT_DIM * KY;
    const int T2 = STATE * IN_DIM;
    float v;
    if (idx < T1) {
        int o = idx / KY, k = idx % KY;
        v = (k < 512) ? g_P[o * STATE + k]
          : (k < 1024) ? g_Q[o * STATE + (k - 512)]
          : g_F[o * IN_DIM + (k - 1024)];
        __nv_bfloat16 h = __float2bfloat16(v);
        g_Wy_hi[idx] = h;
        g_Wy_lo[idx] = __float2bfloat16(v - __bfloat162float(h));
    } else if (idx < T1 + T2) {
        int t = idx - T1;
        int hh = t / IN_DIM, j = t % IN_DIM;
        v = g_G[(2 * hh) * IN_DIM + j];
        __nv_bfloat16 h = __float2bfloat16(v);
        g_Ws_hi[t] = h;
        g_Ws_lo[t] = __float2bfloat16(v - __bfloat162float(h));
    }
}

// ---------------- mma.sync bf16 3-term split GEMM ----------------
// D[128 x 128] = A[128 x K] * W[128 x K]^T, acc fp32 in registers.
// MODE 0: y   (A = [x0_re|x0_im|u], W = g_Wy, K=1280)
// MODE 2: s_re (A = u, W = g_Ws, K=256; epilogue Re(lam*x0), clamped to lim)
// Weight matrices are selected IN DEVICE CODE by MODE (host shadow addresses are invalid on ATS).
#define ROWE 40      // smem row stride in bf16 elems (80 B)
#define SA_HI 0
#define SA_LO (128 * ROWE)
#define SW_HI (2 * 128 * ROWE)
#define SW_LO (3 * 128 * ROWE)

template <int MODE>
__global__ __launch_bounds__(256)
void k_mma(const float* __restrict__ A0, const float* __restrict__ A1, const float* __restrict__ A2,
           const float* __restrict__ x0_re, const float* __restrict__ x0_im,
           float* __restrict__ out, long long lim) {
    constexpr int KT = (MODE == 0) ? KY : IN_DIM;
    const __nv_bfloat16* __restrict__ Wh = (MODE == 0) ? g_Wy_hi : g_Ws_hi;
    const __nv_bfloat16* __restrict__ Wl = (MODE == 0) ? g_Wy_lo : g_Ws_lo;

    __shared__ __nv_bfloat16 sm[4 * 128 * ROWE];   // A_hi | A_lo | W_hi | W_lo (40960 B)
    uint32_t sb = smem_u32(sm);

    int tid  = threadIdx.x;
    int wid  = tid >> 5;
    int lane = tid & 31;
    int m0 = blockIdx.x * 128;
    int n0 = blockIdx.y * 128;
    int wm = wid & 1;          // 2 warps over M (64 rows each)
    int wn = wid >> 1;         // 4 warps over N (32 cols each)

    float acc[4][4][4];
#pragma unroll
    for (int i = 0; i < 4; i++)
#pragma unroll
        for (int j = 0; j < 4; j++)
#pragma unroll
            for (int q = 0; q < 4; q++) acc[i][j][q] = 0.f;

    int lr_  = tid >> 1;        // loader row (0..127)
    int half = tid & 1;         // k-half (16 elems)

#pragma unroll 1
    for (int k0 = 0; k0 < KT; k0 += 32) {
        // segment select for A
        const float* Ag;
        int astr;
        if (MODE == 0) {
            if (k0 < 512)       { Ag = A0 + k0;          astr = STATE; }
            else if (k0 < 1024) { Ag = A1 + (k0 - 512);  astr = STATE; }
            else                { Ag = A2 + (k0 - 1024); astr = IN_DIM; }
        } else { Ag = A0 + k0; astr = IN_DIM; }

        // ---- A tile 128x32 fp32 -> bf16 hi/lo in smem ----
        {
            const float* p = Ag + (size_t)(m0 + lr_) * astr + half * 16;
            float4 v0 = *(const float4*)(p);
            float4 v1 = *(const float4*)(p + 4);
            float4 v2 = *(const float4*)(p + 8);
            float4 v3 = *(const float4*)(p + 12);
            float xs[16] = {v0.x, v0.y, v0.z, v0.w, v1.x, v1.y, v1.z, v1.w,
                            v2.x, v2.y, v2.z, v2.w, v3.x, v3.y, v3.z, v3.w};
            uint32_t hu[8], lu[8];
#pragma unroll
            for (int q = 0; q < 8; q++) {
                __nv_bfloat16 h0 = __float2bfloat16(xs[2 * q]);
                __nv_bfloat16 h1 = __float2bfloat16(xs[2 * q + 1]);
                uint32_t l0 = __bfloat16_as_ushort(__float2bfloat16(xs[2 * q]     - __bfloat162float(h0)));
                uint32_t l1 = __bfloat16_as_ushort(__float2bfloat16(xs[2 * q + 1] - __bfloat162float(h1)));
                hu[q] = (uint32_t)__bfloat16_as_ushort(h0) | ((uint32_t)__bfloat16_as_ushort(h1) << 16);
                lu[q] = l0 | (l1 << 16);
            }
            uint32_t base = lr_ * (ROWE * 2) + half * 32;
            sts128(sb + SA_HI * 2 + base,      hu[0], hu[1], hu[2], hu[3]);
            sts128(sb + SA_HI * 2 + base + 16, hu[4], hu[5], hu[6], hu[7]);
            sts128(sb + SA_LO * 2 + base,      lu[0], lu[1], lu[2], lu[3]);
            sts128(sb + SA_LO * 2 + base + 16, lu[4], lu[5], lu[6], lu[7]);
        }
        // ---- W tile 128x32 bf16 hi/lo -> smem ----
        {
            size_t off = (size_t)(n0 + lr_) * KT + k0 + half * 16;
            uint4 vh0 = *(const uint4*)(Wh + off);
            uint4 vh1 = *(const uint4*)(Wh + off + 8);
            uint4 vl0 = *(const uint4*)(Wl + off);
            uint4 vl1 = *(const uint4*)(Wl + off + 8);
            uint32_t base = lr_ * (ROWE * 2) + half * 32;
            sts128(sb + SW_HI * 2 + base,      vh0.x, vh0.y, vh0.z, vh0.w);
            sts128(sb + SW_HI * 2 + base + 16, vh1.x, vh1.y, vh1.z, vh1.w);
            sts128(sb + SW_LO * 2 + base,      vl0.x, vl0.y, vl0.z, vl0.w);
            sts128(sb + SW_LO * 2 + base + 16, vl1.x, vl1.y, vl1.z, vl1.w);
        }
        __syncthreads();

        // ---- 2 k-steps of 16 ----
#pragma unroll
        for (int ks = 0; ks < 2; ks++) {
            uint32_t ah[4][4], al[4][4], bh[4][2], bl[4][2];
            uint32_t acol = ks * 32 + (lane >> 4) * 16;   // bytes
#pragma unroll
            for (int mt = 0; mt < 4; mt++) {
                uint32_t r = wm * 64 + mt * 16 + (lane & 15);
                uint32_t ad = r * (ROWE * 2) + acol;
                ldm_x4(ah[mt], sb + SA_HI * 2 + ad);
                ldm_x4(al[mt], sb + SA_LO * 2 + ad);
            }
            uint32_t bcol = ks * 32 + ((lane >> 3) & 1) * 16;
#pragma unroll
            for (int nt = 0; nt < 4; nt++) {
                uint32_t n = wn * 32 + nt * 8 + (lane & 7);
                uint32_t bd = n * (ROWE * 2) + bcol;
                ldm_x2(bh[nt], sb + SW_HI * 2 + bd);
                ldm_x2(bl[nt], sb + SW_LO * 2 + bd);
            }
#pragma unroll
            for (int mt = 0; mt < 4; mt++)
#pragma unroll
                for (int nt = 0; nt < 4; nt++) {
                    mma_bf16(acc[mt][nt], ah[mt], bh[nt]);
                    mma_bf16(acc[mt][nt], ah[mt], bl[nt]);
                    mma_bf16(acc[mt][nt], al[mt], bh[nt]);
                }
        }
        __syncthreads();
    }

    // ---- epilogue ----
    int rbase = m0 + wm * 64 + (lane >> 2);
    int cbase = n0 + wn * 32 + 2 * (lane & 3);
#pragma unroll
    for (int mt = 0; mt < 4; mt++) {
#pragma unroll
        for (int nt = 0; nt < 4; nt++) {
            int col = cbase + nt * 8;
#pragma unroll
            for (int hrow = 0; hrow < 2; hrow++) {
                int row = rbase + mt * 16 + hrow * 8;
                float v0 = acc[mt][nt][2 * hrow];
                float v1 = acc[mt][nt][2 * hrow + 1];
                if (MODE == 0) {
                    float2* dst = (float2*)(out + (size_t)row * OUT_DIM + col);
                    *dst = make_float2(v0, v1);
                } else {
                    long long idx = (long long)row * STATE + col;
                    if (idx + 1 < lim) {
                        float2 lr2 = *(const float2*)&g_lam_re[col];
                        float2 li2 = *(const float2*)&g_lam_im[col];
                        float2 xr  = *(const float2*)&x0_re[(size_t)row * STATE + col];
                        float2 xi  = *(const float2*)&x0_im[(size_t)row * STATE + col];
                        float2 o2;
                        o2.x = lr2.x * xr.x - li2.x * xi.x + v0;
                        o2.y = lr2.y * xr.y - li2.y * xi.y + v1;
                        *(float2*)(out + idx) = o2;
                    }
                }
            }
        }
    }
}

// ---------------- legacy fp32 GEMM, kept ONLY for interleaved-c64 state fallback ----
__global__ __launch_bounds__(256)
void k_gemm_c64(const float* __restrict__ A0, int K0,
                const float* __restrict__ x0_re, const float* __restrict__ x0_im,
                float* __restrict__ out, long long lim) {
    const int BM = 128, BN = 64, BK = 16;
    __shared__ float As[BK][BM + 4];
    __shared__ float Bs[BK][BN + 4];
    int tid = threadIdx.x;
    int m0 = blockIdx.x * BM;
    int n0 = blockIdx.y * BN;
    int tx = tid & 15, ty = tid >> 4;
    float acc[8][4];
#pragma unroll
    for (int i = 0; i < 8; i++)
#pragma unroll
        for (int j = 0; j < 4; j++) acc[i][j] = 0.f;

#pragma unroll 1
    for (int k0 = 0; k0 < K0; k0 += BK) {
#pragma unroll
        for (int l = 0; l < 2; l++) {
            int f = tid + l * 256;
            int r = f >> 2, kk4 = (f & 3) * 4;
            float4 v = *(const float4*)&A0[(size_t)(m0 + r) * K0 + k0 + kk4];
            As[kk4 + 0][r] = v.x; As[kk4 + 1][r] = v.y;
            As[kk4 + 2][r] = v.z; As[kk4 + 3][r] = v.w;
        }
        {
            int n = tid >> 2, kk4 = (tid & 3) * 4;
            float4 v = *(const float4*)&g_G[(size_t)(n0 + n) * K0 + k0 + kk4];
            Bs[kk4 + 0][n] = v.x; Bs[kk4 + 1][n] = v.y;
            Bs[kk4 + 2][n] = v.z; Bs[kk4 + 3][n] = v.w;
        }
        __syncthreads();
#pragma unroll
        for (int kk = 0; kk < BK; kk++) {
            float4 b  = *(const float4*)&Bs[kk][tx * 4];
            float4 a0 = *(const float4*)&As[kk][ty * 8];
            float4 a1 = *(const float4*)&As[kk][ty * 8 + 4];
            float av[8] = {a0.x, a0.y, a0.z, a0.w, a1.x, a1.y, a1.z, a1.w};
            float bv[4] = {b.x, b.y, b.z, b.w};
#pragma unroll
            for (int i = 0; i < 8; i++)
#pragma unroll
                for (int j = 0; j < 4; j++) acc[i][j] += av[i] * bv[j];
        }
        __syncthreads();
    }
    int c0 = n0 + tx * 4;
    int h0 = c0 >> 1;
    float lr0 = g_lam_re[h0],     li0 = g_lam_im[h0];
    float lr1 = g_lam_re[h0 + 1], li1 = g_lam_im[h0 + 1];
#pragma unroll
    for (int i = 0; i < 8; i++) {
        int row = m0 + ty * 8 + i;
        long long idx = (long long)row * (2 * STATE) + c0;
        if (idx + 3 < lim) {
            float xr0 = x0_re[(size_t)row * STATE + h0];
            float xi0 = x0_im[(size_t)row * STATE + h0];
            float xr1 = x0_re[(size_t)row * STATE + h0 + 1];
            float xi1 = x0_im[(size_t)row * STATE + h0 + 1];
            float4 v;
            v.x = lr0 * xr0 - li0 * xi0 + acc[i][0];
            v.y = lr0 * xi0 + li0 * xr0 + acc[i][1];
            v.z = lr1 * xr1 - li1 * xi1 + acc[i][2];
            v.w = lr1 * xi1 + li1 * xr1 + acc[i][3];
            *(float4*)&out[idx] = v;
        }
    }
}

// ---------------- launch ----------------
extern "C" void kernel_launch(void* const* d_in, const int* in_sizes, int n_in,
                              void* d_out, int out_size) {
    const long long expect[11] = {
        (long long)NSEQ * IN_DIM, (long long)NSEQ * STATE, (long long)NSEQ * STATE,
        STATE, STATE, STATE,
        (long long)STATE * IN_DIM, (long long)STATE * IN_DIM,
        (long long)OUT_DIM * STATE, (long long)OUT_DIM * STATE,
        (long long)OUT_DIM * IN_DIM
    };
    const float* ptr[11];
    bool used[32] = {false};
    for (int e = 0; e < 11; e++) {
        ptr[e] = nullptr;
        for (int i = 0; i < n_in; i++) {
            if (!used[i] && (long long)in_sizes[i] == expect[e]) {
                ptr[e] = (const float*)d_in[i];
                used[i] = true;
                break;
            }
        }
        if (!ptr[e]) ptr[e] = (const float*)d_in[e < n_in ? e : 0];
    }
    const float* u         = ptr[0];
    const float* x0_re     = ptr[1];
    const float* x0_im     = ptr[2];
    const float* nu_log    = ptr[3];
    const float* theta_log = ptr[4];
    const float* gamma_log = ptr[5];
    const float* B_re      = ptr[6];
    const float* B_im      = ptr[7];
    const float* C_re      = ptr[8];
    const float* C_im      = ptr[9];
    const float* D         = ptr[10];
    float* out = (float*)d_out;

    k_lam<<<1, STATE>>>(nu_log, theta_log, gamma_log);
    int tot = 2 * STATE * IN_DIM + OUT_DIM * STATE;
    k_weights<<<(tot + 255) / 256, 256>>>(B_re, B_im, C_re, C_im);
    k_F<<<dim3(IN_DIM / 16, OUT_DIM / 16), dim3(16, 16)>>>(C_re, C_im, D);
    int tots = OUT_DIM * KY + STATE * IN_DIM;
    k_split<<<(tots + 255) / 256, 256>>>();

    const long long Y_ELEMS      = (long long)NSEQ * OUT_DIM;   //  8,388,608
    const long long ST_C64_ELEMS = (long long)NSEQ * 2 * STATE; // 33,554,432
    const long long ST_RE_ELEMS  = (long long)NSEQ * STATE;     // 16,777,216
    long long cap = (long long)out_size;
    if (cap == Y_ELEMS / 2 + ST_C64_ELEMS / 2) cap *= 2;        // c64-counted case

    // y: [N,1280] x [1280,256]
    k_mma<0><<<dim3(NSEQ / 128, OUT_DIM / 128), 256>>>(
        x0_re, x0_im, u, nullptr, nullptr, out, Y_ELEMS);

    float* out_state = out + Y_ELEMS;
    long long rem = cap - Y_ELEMS;
    if (rem >= ST_C64_ELEMS) {
        k_gemm_c64<<<dim3(NSEQ / 128, (2 * STATE) / 64), 256>>>(
            u, IN_DIM, x0_re, x0_im, out_state, rem);
    } else if (rem >= ST_RE_ELEMS) {
        // real-part-only state plane (confirmed layout)
        k_mma<2><<<dim3(NSEQ / 128, STATE / 128), 256>>>(
            u, nullptr, nullptr, x0_re, x0_im, out_state, rem);
    }
}

// round 9
// speedup vs baseline: 1.7698x; 1.0672x over previous
#include <cuda_runtime.h>
#include <cuda_bf16.h>
#include <math.h>
#include <stdint.h>

#define IN_DIM   256
#define STATE    512
#define OUT_DIM  256
#define NSEQ     32768
#define KY       1280   // x0_re(512) | x0_im(512) | u(256)

// ---------------- device scratch (no allocation allowed), 16B-aligned ----------------
__device__ __align__(16) float g_lam_re[STATE];
__device__ __align__(16) float g_lam_im[STATE];
__device__ __align__(16) float g_gam[STATE];
__device__ __align__(16) float g_G[2 * STATE * IN_DIM];  // [1024,256] fp32
__device__ __align__(16) float g_P[OUT_DIM * STATE];
__device__ __align__(16) float g_Q[OUT_DIM * STATE];
__device__ __align__(16) float g_F[OUT_DIM * IN_DIM];
// bf16 hi/lo split weights (ONLY referenced from device code — host shadow address is invalid!)
__device__ __align__(16) __nv_bfloat16 g_Wy_hi[OUT_DIM * KY];
__device__ __align__(16) __nv_bfloat16 g_Wy_lo[OUT_DIM * KY];
__device__ __align__(16) __nv_bfloat16 g_Ws_hi[STATE * IN_DIM];
__device__ __align__(16) __nv_bfloat16 g_Ws_lo[STATE * IN_DIM];

// ---------------- PTX helpers (sm_80-era; legal on compute_103) ----------------
__device__ __forceinline__ uint32_t smem_u32(const void* p) {
    uint32_t a;
    asm("{ .reg .u64 t; cvta.to.shared.u64 t, %1; cvt.u32.u64 %0, t; }" : "=r"(a) : "l"(p));
    return a;
}
__device__ __forceinline__ void sts128(uint32_t a, uint32_t x, uint32_t y, uint32_t z, uint32_t w) {
    asm volatile("st.shared.v4.b32 [%0], {%1,%2,%3,%4};" :: "r"(a), "r"(x), "r"(y), "r"(z), "r"(w) : "memory");
}
__device__ __forceinline__ void cp16(uint32_t dst, const void* src) {
    asm volatile("cp.async.cg.shared.global [%0], [%1], 16;" :: "r"(dst), "l"(src) : "memory");
}
__device__ __forceinline__ void cp_commit_wait() {
    asm volatile("cp.async.commit_group;" ::: "memory");
    asm volatile("cp.async.wait_group 0;" ::: "memory");
}
__device__ __forceinline__ void ldm_x4(uint32_t* r, uint32_t addr) {
    asm volatile("ldmatrix.sync.aligned.m8n8.x4.shared.b16 {%0,%1,%2,%3}, [%4];"
        : "=r"(r[0]), "=r"(r[1]), "=r"(r[2]), "=r"(r[3]) : "r"(addr));
}
__device__ __forceinline__ void ldm_x2(uint32_t* r, uint32_t addr) {
    asm volatile("ldmatrix.sync.aligned.m8n8.x2.shared.b16 {%0,%1}, [%2];"
        : "=r"(r[0]), "=r"(r[1]) : "r"(addr));
}
__device__ __forceinline__ void mma_bf16(float* c, const uint32_t* a, const uint32_t* b) {
    asm volatile(
        "mma.sync.aligned.m16n8k16.row.col.f32.bf16.bf16.f32 "
        "{%0,%1,%2,%3}, {%4,%5,%6,%7}, {%8,%9}, {%0,%1,%2,%3};"
        : "+f"(c[0]), "+f"(c[1]), "+f"(c[2]), "+f"(c[3])
        : "r"(a[0]), "r"(a[1]), "r"(a[2]), "r"(a[3]), "r"(b[0]), "r"(b[1]));
}

// ---------------- tiny precompute kernels ----------------
__global__ void k_lam(const float* __restrict__ nu_log,
                      const float* __restrict__ theta_log,
                      const float* __restrict__ gamma_log) {
    int h = threadIdx.x;
    float mod = expf(-expf(nu_log[h]));
    float th  = expf(theta_log[h]);
    g_lam_re[h] = mod * cosf(th);
    g_lam_im[h] = mod * sinf(th);
    g_gam[h]    = expf(gamma_log[h]);
}

__global__ void k_weights(const float* __restrict__ B_re, const float* __restrict__ B_im,
                          const float* __restrict__ C_re, const float* __restrict__ C_im) {
    int idx = blockIdx.x * blockDim.x + threadIdx.x;
    const int NG = 2 * STATE * IN_DIM;
    const int NP = OUT_DIM * STATE;
    if (idx < NG) {
        int c = idx / IN_DIM, j = idx % IN_DIM, h = c >> 1;
        float b = (c & 1) ? B_im[h * IN_DIM + j] : B_re[h * IN_DIM + j];
        g_G[idx] = b * g_gam[h];
    } else if (idx < NG + NP) {
        int t = idx - NG;
        int o = t / STATE, h = t % STATE;
        float cr = C_re[o * STATE + h], ci = C_im[o * STATE + h];
        float lr = g_lam_re[h], li = g_lam_im[h];
        g_P[t] = lr * cr - li * ci;
        g_Q[t] = -(li * cr + lr * ci);
    }
}

__global__ void k_F(const float* __restrict__ C_re, const float* __restrict__ C_im,
                    const float* __restrict__ D) {
    __shared__ float sCr[16][16], sCi[16][16], sGr[16][17], sGi[16][17];
    int o0 = blockIdx.y * 16, j0 = blockIdx.x * 16;
    int tx = threadIdx.x, ty = threadIdx.y;
    float acc = 0.f;
    for (int h0 = 0; h0 < STATE; h0 += 16) {
        sCr[ty][tx] = C_re[(o0 + ty) * STATE + h0 + tx];
        sCi[ty][tx] = C_im[(o0 + ty) * STATE + h0 + tx];
        sGr[ty][tx] = g_G[(2 * (h0 + ty)) * IN_DIM + j0 + tx];
        sGi[ty][tx] = g_G[(2 * (h0 + ty) + 1) * IN_DIM + j0 + tx];
        __syncthreads();
#pragma unroll
        for (int k = 0; k < 16; k++)
            acc += sCr[ty][k] * sGr[k][tx] - sCi[ty][k] * sGi[k][tx];
        __syncthreads();
    }
    g_F[(o0 + ty) * IN_DIM + j0 + tx] = D[(o0 + ty) * IN_DIM + j0 + tx] + acc;
}

__global__ void k_split() {
    int idx = blockIdx.x * blockDim.x + threadIdx.x;
    const int T1 = OUT_DIM * KY;
    const int T2 = STATE * IN_DIM;
    float v;
    if (idx < T1) {
        int o = idx / KY, k = idx % KY;
        v = (k < 512) ? g_P[o * STATE + k]
          : (k < 1024) ? g_Q[o * STATE + (k - 512)]
          : g_F[o * IN_DIM + (k - 1024)];
        __nv_bfloat16 h = __float2bfloat16(v);
        g_Wy_hi[idx] = h;
        g_Wy_lo[idx] = __float2bfloat16(v - __bfloat162float(h));
    } else if (idx < T1 + T2) {
        int t = idx - T1;
        int hh = t / IN_DIM, j = t % IN_DIM;
        v = g_G[(2 * hh) * IN_DIM + j];
        __nv_bfloat16 h = __float2bfloat16(v);
        g_Ws_hi[t] = h;
        g_Ws_lo[t] = __float2bfloat16(v - __bfloat162float(h));
    }
}

// ---------------- pipelined mma.sync bf16 3-term split GEMM ----------------
// D[128 x 128] = A[128 x K] * W[128 x K]^T, acc fp32 in registers; 2-stage smem pipeline.
// MODE 0: y (A = [x0_re|x0_im|u], W = g_Wy, K=1280); MODE 2: s_re (A = u, W = g_Ws, K=256).
#define ROWE  40                    // smem row stride in bf16 elems (80 B)
#define STG   (4 * 128 * ROWE)      // elems per stage: A_hi | A_lo | W_hi | W_lo
#define SA_HI 0
#define SA_LO (128 * ROWE)
#define SW_HI (2 * 128 * ROWE)
#define SW_LO (3 * 128 * ROWE)
#define SMEM_BYTES (2 * STG * 2)    // 2 stages * STG elems * 2 B = 81920

template <int MODE>
__global__ __launch_bounds__(256, 1)
void k_mma(const float* __restrict__ A0, const float* __restrict__ A1, const float* __restrict__ A2,
           const float* __restrict__ x0_re, const float* __restrict__ x0_im,
           float* __restrict__ out, long long lim) {
    constexpr int KT = (MODE == 0) ? KY : IN_DIM;
    const __nv_bfloat16* __restrict__ Wh = (MODE == 0) ? g_Wy_hi : g_Ws_hi;
    const __nv_bfloat16* __restrict__ Wl = (MODE == 0) ? g_Wy_lo : g_Ws_lo;

    extern __shared__ __nv_bfloat16 sm[];
    uint32_t sb = smem_u32(sm);

    int tid  = threadIdx.x;
    int wid  = tid >> 5;
    int lane = tid & 31;
    int m0 = blockIdx.x * 128;
    int n0 = blockIdx.y * 128;
    int wm = wid & 1;
    int wn = wid >> 1;

    float acc[4][4][4];
#pragma unroll
    for (int i = 0; i < 4; i++)
#pragma unroll
        for (int j = 0; j < 4; j++)
#pragma unroll
            for (int q = 0; q < 4; q++) acc[i][j][q] = 0.f;

    int lr_  = tid >> 1;        // loader row (0..127)
    int half = tid & 1;         // k-half (16 elems)

    // per-iteration helpers ------------------------------------------------
    auto a_ptr = [&](int k0) -> const float* {
        const float* Ag; int astr;
        if (MODE == 0) {
            if (k0 < 512)       { Ag = A0 + k0;          astr = STATE; }
            else if (k0 < 1024) { Ag = A1 + (k0 - 512);  astr = STATE; }
            else                { Ag = A2 + (k0 - 1024); astr = IN_DIM; }
        } else { Ag = A0 + k0; astr = IN_DIM; }
        return Ag + (size_t)(m0 + lr_) * astr + half * 16;
    };

    float4 pv0, pv1, pv2, pv3;                 // A prefetch registers
    uint32_t ldbase = lr_ * (ROWE * 2) + half * 32;

    auto issue_w = [&](int k0, uint32_t stg) {
        size_t off = (size_t)(n0 + lr_) * KT + k0 + half * 16;
        uint32_t b = sb + stg * 2 + ldbase;
        cp16(b + SW_HI * 2,      Wh + off);
        cp16(b + SW_HI * 2 + 16, Wh + off + 8);
        cp16(b + SW_LO * 2,      Wl + off);
        cp16(b + SW_LO * 2 + 16, Wl + off + 8);
    };
    auto load_a = [&](int k0) {
        const float* p = a_ptr(k0);
        pv0 = *(const float4*)(p);
        pv1 = *(const float4*)(p + 4);
        pv2 = *(const float4*)(p + 8);
        pv3 = *(const float4*)(p + 12);
    };
    auto store_a = [&](uint32_t stg) {
        float xs[16] = {pv0.x, pv0.y, pv0.z, pv0.w, pv1.x, pv1.y, pv1.z, pv1.w,
                        pv2.x, pv2.y, pv2.z, pv2.w, pv3.x, pv3.y, pv3.z, pv3.w};
        uint32_t hu[8], lu[8];
#pragma unroll
        for (int q = 0; q < 8; q++) {
            __nv_bfloat16 h0 = __float2bfloat16(xs[2 * q]);
            __nv_bfloat16 h1 = __float2bfloat16(xs[2 * q + 1]);
            uint32_t l0 = __bfloat16_as_ushort(__float2bfloat16(xs[2 * q]     - __bfloat162float(h0)));
            uint32_t l1 = __bfloat16_as_ushort(__float2bfloat16(xs[2 * q + 1] - __bfloat162float(h1)));
            hu[q] = (uint32_t)__bfloat16_as_ushort(h0) | ((uint32_t)__bfloat16_as_ushort(h1) << 16);
            lu[q] = l0 | (l1 << 16);
        }
        uint32_t b = sb + stg * 2 + ldbase;
        sts128(b + SA_HI * 2,      hu[0], hu[1], hu[2], hu[3]);
        sts128(b + SA_HI * 2 + 16, hu[4], hu[5], hu[6], hu[7]);
        sts128(b + SA_LO * 2,      lu[0], lu[1], lu[2], lu[3]);
        sts128(b + SA_LO * 2 + 16, lu[4], lu[5], lu[6], lu[7]);
    };

    // ---- prologue: fill stage 0 ----
    load_a(0);
    issue_w(0, 0);
    store_a(0);
    cp_commit_wait();
    __syncthreads();

    // ---- main loop, one barrier per chunk ----
#pragma unroll 1
    for (int k0 = 0; k0 < KT; k0 += 32) {
        uint32_t cur = (uint32_t)((k0 >> 5) & 1) * STG;
        uint32_t nxt = STG - cur;
        bool more = (k0 + 32) < KT;
        if (more) {                       // issue next-chunk loads FIRST (hide behind MMA)
            load_a(k0 + 32);
            issue_w(k0 + 32, nxt);
        }

        uint32_t sc = sb + cur * 2;
#pragma unroll
        for (int ks = 0; ks < 2; ks++) {
            uint32_t ah[4][4], al[4][4], bh[4][2], bl[4][2];
            uint32_t acol = ks * 32 + (lane >> 4) * 16;
#pragma unroll
            for (int mt = 0; mt < 4; mt++) {
                uint32_t r = wm * 64 + mt * 16 + (lane & 15);
                uint32_t ad = r * (ROWE * 2) + acol;
                ldm_x4(ah[mt], sc + SA_HI * 2 + ad);
                ldm_x4(al[mt], sc + SA_LO * 2 + ad);
            }
            uint32_t bcol = ks * 32 + ((lane >> 3) & 1) * 16;
#pragma unroll
            for (int nt = 0; nt < 4; nt++) {
                uint32_t n = wn * 32 + nt * 8 + (lane & 7);
                uint32_t bd = n * (ROWE * 2) + bcol;
                ldm_x2(bh[nt], sc + SW_HI * 2 + bd);
                ldm_x2(bl[nt], sc + SW_LO * 2 + bd);
            }
#pragma unroll
            for (int mt = 0; mt < 4; mt++)
#pragma unroll
                for (int nt = 0; nt < 4; nt++) {
                    mma_bf16(acc[mt][nt], ah[mt], bh[nt]);
                    mma_bf16(acc[mt][nt], ah[mt], bl[nt]);
                    mma_bf16(acc[mt][nt], al[mt], bh[nt]);
                }
        }

        if (more) {
            store_a(nxt);                 // regs -> next stage (nobody reads nxt this iter)
            cp_commit_wait();
        }
        __syncthreads();
    }

    // ---- epilogue ----
    int rbase = m0 + wm * 64 + (lane >> 2);
    int cbase = n0 + wn * 32 + 2 * (lane & 3);
#pragma unroll
    for (int mt = 0; mt < 4; mt++) {
#pragma unroll
        for (int nt = 0; nt < 4; nt++) {
            int col = cbase + nt * 8;
#pragma unroll
            for (int hrow = 0; hrow < 2; hrow++) {
                int row = rbase + mt * 16 + hrow * 8;
                float v0 = acc[mt][nt][2 * hrow];
                float v1 = acc[mt][nt][2 * hrow + 1];
                if (MODE == 0) {
                    float2* dst = (float2*)(out + (size_t)row * OUT_DIM + col);
                    *dst = make_float2(v0, v1);
                } else {
                    long long idx = (long long)row * STATE + col;
                    if (idx + 1 < lim) {
                        float2 lr2 = *(const float2*)&g_lam_re[col];
                        float2 li2 = *(const float2*)&g_lam_im[col];
                        float2 xr  = *(const float2*)&x0_re[(size_t)row * STATE + col];
                        float2 xi  = *(const float2*)&x0_im[(size_t)row * STATE + col];
                        float2 o2;
                        o2.x = lr2.x * xr.x - li2.x * xi.x + v0;
                        o2.y = lr2.y * xr.y - li2.y * xi.y + v1;
                        *(float2*)(out + idx) = o2;
                    }
                }
            }
        }
    }
}

// ---------------- legacy fp32 GEMM (interleaved-c64 state fallback only) ----------------
__global__ __launch_bounds__(256)
void k_gemm_c64(const float* __restrict__ A0, int K0,
                const float* __restrict__ x0_re, const float* __restrict__ x0_im,
                float* __restrict__ out, long long lim) {
    const int BM = 128, BN = 64, BK = 16;
    __shared__ float As[BK][BM + 4];
    __shared__ float Bs[BK][BN + 4];
    int tid = threadIdx.x;
    int m0 = blockIdx.x * BM;
    int n0 = blockIdx.y * BN;
    int tx = tid & 15, ty = tid >> 4;
    float acc[8][4];
#pragma unroll
    for (int i = 0; i < 8; i++)
#pragma unroll
        for (int j = 0; j < 4; j++) acc[i][j] = 0.f;

#pragma unroll 1
    for (int k0 = 0; k0 < K0; k0 += BK) {
#pragma unroll
        for (int l = 0; l < 2; l++) {
            int f = tid + l * 256;
            int r = f >> 2, kk4 = (f & 3) * 4;
            float4 v = *(const float4*)&A0[(size_t)(m0 + r) * K0 + k0 + kk4];
            As[kk4 + 0][r] = v.x; As[kk4 + 1][r] = v.y;
            As[kk4 + 2][r] = v.z; As[kk4 + 3][r] = v.w;
        }
        {
            int n = tid >> 2, kk4 = (tid & 3) * 4;
            float4 v = *(const float4*)&g_G[(size_t)(n0 + n) * K0 + k0 + kk4];
            Bs[kk4 + 0][n] = v.x; Bs[kk4 + 1][n] = v.y;
            Bs[kk4 + 2][n] = v.z; Bs[kk4 + 3][n] = v.w;
        }
        __syncthreads();
#pragma unroll
        for (int kk = 0; kk < BK; kk++) {
            float4 b  = *(const float4*)&Bs[kk][tx * 4];
            float4 a0 = *(const float4*)&As[kk][ty * 8];
            float4 a1 = *(const float4*)&As[kk][ty * 8 + 4];
            float av[8] = {a0.x, a0.y, a0.z, a0.w, a1.x, a1.y, a1.z, a1.w};
            float bv[4] = {b.x, b.y, b.z, b.w};
#pragma unroll
            for (int i = 0; i < 8; i++)
#pragma unroll
                for (int j = 0; j < 4; j++) acc[i][j] += av[i] * bv[j];
        }
        __syncthreads();
    }
    int c0 = n0 + tx * 4;
    int h0 = c0 >> 1;
    float lr0 = g_lam_re[h0],     li0 = g_lam_im[h0];
    float lr1 = g_lam_re[h0 + 1], li1 = g_lam_im[h0 + 1];
#pragma unroll
    for (int i = 0; i < 8; i++) {
        int row = m0 + ty * 8 + i;
        long long idx = (long long)row * (2 * STATE) + c0;
        if (idx + 3 < lim) {
            float xr0 = x0_re[(size_t)row * STATE + h0];
            float xi0 = x0_im[(size_t)row * STATE + h0];
            float xr1 = x0_re[(size_t)row * STATE + h0 + 1];
            float xi1 = x0_im[(size_t)row * STATE + h0 + 1];
            float4 v;
            v.x = lr0 * xr0 - li0 * xi0 + acc[i][0];
            v.y = lr0 * xi0 + li0 * xr0 + acc[i][1];
            v.z = lr1 * xr1 - li1 * xi1 + acc[i][2];
            v.w = lr1 * xi1 + li1 * xr1 + acc[i][3];
            *(float4*)&out[idx] = v;
        }
    }
}

// ---------------- launch ----------------
extern "C" void kernel_launch(void* const* d_in, const int* in_sizes, int n_in,
                              void* d_out, int out_size) {
    const long long expect[11] = {
        (long long)NSEQ * IN_DIM, (long long)NSEQ * STATE, (long long)NSEQ * STATE,
        STATE, STATE, STATE,
        (long long)STATE * IN_DIM, (long long)STATE * IN_DIM,
        (long long)OUT_DIM * STATE, (long long)OUT_DIM * STATE,
        (long long)OUT_DIM * IN_DIM
    };
    const float* ptr[11];
    bool used[32] = {false};
    for (int e = 0; e < 11; e++) {
        ptr[e] = nullptr;
        for (int i = 0; i < n_in; i++) {
            if (!used[i] && (long long)in_sizes[i] == expect[e]) {
                ptr[e] = (const float*)d_in[i];
                used[i] = true;
                break;
            }
        }
        if (!ptr[e]) ptr[e] = (const float*)d_in[e < n_in ? e : 0];
    }
    const float* u         = ptr[0];
    const float* x0_re     = ptr[1];
    const float* x0_im     = ptr[2];
    const float* nu_log    = ptr[3];
    const float* theta_log = ptr[4];
    const float* gamma_log = ptr[5];
    const float* B_re      = ptr[6];
    const float* B_im      = ptr[7];
    const float* C_re      = ptr[8];
    const float* C_im      = ptr[9];
    const float* D         = ptr[10];
    float* out = (float*)d_out;

    static int attr_done = 0;
    if (!attr_done) {
        cudaFuncSetAttribute(k_mma<0>, cudaFuncAttributeMaxDynamicSharedMemorySize, SMEM_BYTES);
        cudaFuncSetAttribute(k_mma<2>, cudaFuncAttributeMaxDynamicSharedMemorySize, SMEM_BYTES);
        attr_done = 1;
    }

    k_lam<<<1, STATE>>>(nu_log, theta_log, gamma_log);
    int tot = 2 * STATE * IN_DIM + OUT_DIM * STATE;
    k_weights<<<(tot + 255) / 256, 256>>>(B_re, B_im, C_re, C_im);
    k_F<<<dim3(IN_DIM / 16, OUT_DIM / 16), dim3(16, 16)>>>(C_re, C_im, D);
    int tots = OUT_DIM * KY + STATE * IN_DIM;
    k_split<<<(tots + 255) / 256, 256>>>();

    const long long Y_ELEMS      = (long long)NSEQ * OUT_DIM;   //  8,388,608
    const long long ST_C64_ELEMS = (long long)NSEQ * 2 * STATE; // 33,554,432
    const long long ST_RE_ELEMS  = (long long)NSEQ * STATE;     // 16,777,216
    long long cap = (long long)out_size;
    if (cap == Y_ELEMS / 2 + ST_C64_ELEMS / 2) cap *= 2;        // c64-counted case

    // y: [N,1280] x [1280,256]
    k_mma<0><<<dim3(NSEQ / 128, OUT_DIM / 128), 256, SMEM_BYTES>>>(
        x0_re, x0_im, u, nullptr, nullptr, out, Y_ELEMS);

    float* out_state = out + Y_ELEMS;
    long long rem = cap - Y_ELEMS;
    if (rem >= ST_C64_ELEMS) {
        k_gemm_c64<<<dim3(NSEQ / 128, (2 * STATE) / 64), 256>>>(
            u, IN_DIM, x0_re, x0_im, out_state, rem);
    } else if (rem >= ST_RE_ELEMS) {
        // real-part-only state plane (confirmed layout)
        k_mma<2><<<dim3(NSEQ / 128, STATE / 128), 256, SMEM_BYTES>>>(
            u, nullptr, nullptr, x0_re, x0_im, out_state, rem);
    }
}

// round 10
// speedup vs baseline: 1.8499x; 1.0453x over previous
#include <cuda_runtime.h>
#include <cuda_bf16.h>
#include <math.h>
#include <stdint.h>

#define IN_DIM   256
#define STATE    512
#define OUT_DIM  256
#define NSEQ     32768
#define KY       1280   // x0_re(512) | x0_im(512) | u(256)

// ---------------- device scratch (no allocation allowed), 16B-aligned ----------------
__device__ __align__(16) float g_lam_re[STATE];
__device__ __align__(16) float g_lam_im[STATE];
__device__ __align__(16) float g_gam[STATE];
__device__ __align__(16) float g_G[2 * STATE * IN_DIM];  // [1024,256] fp32 (k_F + c64 fallback)
// bf16 hi/lo split weights (ONLY referenced from device code — host shadow address invalid on ATS)
__device__ __align__(16) __nv_bfloat16 g_Wy_hi[OUT_DIM * KY];
__device__ __align__(16) __nv_bfloat16 g_Wy_lo[OUT_DIM * KY];
__device__ __align__(16) __nv_bfloat16 g_Ws_hi[STATE * IN_DIM];
__device__ __align__(16) __nv_bfloat16 g_Ws_lo[STATE * IN_DIM];

// ---------------- PTX helpers (sm_80-era; legal on compute_103) ----------------
__device__ __forceinline__ uint32_t smem_u32(const void* p) {
    uint32_t a;
    asm("{ .reg .u64 t; cvta.to.shared.u64 t, %1; cvt.u32.u64 %0, t; }" : "=r"(a) : "l"(p));
    return a;
}
__device__ __forceinline__ void sts128(uint32_t a, uint32_t x, uint32_t y, uint32_t z, uint32_t w) {
    asm volatile("st.shared.v4.b32 [%0], {%1,%2,%3,%4};" :: "r"(a), "r"(x), "r"(y), "r"(z), "r"(w) : "memory");
}
__device__ __forceinline__ void cp16(uint32_t dst, const void* src) {
    asm volatile("cp.async.cg.shared.global [%0], [%1], 16;" :: "r"(dst), "l"(src) : "memory");
}
__device__ __forceinline__ void cp_commit_wait() {
    asm volatile("cp.async.commit_group;" ::: "memory");
    asm volatile("cp.async.wait_group 0;" ::: "memory");
}
__device__ __forceinline__ void ldm_x4(uint32_t* r, uint32_t addr) {
    asm volatile("ldmatrix.sync.aligned.m8n8.x4.shared.b16 {%0,%1,%2,%3}, [%4];"
        : "=r"(r[0]), "=r"(r[1]), "=r"(r[2]), "=r"(r[3]) : "r"(addr));
}
__device__ __forceinline__ void ldm_x2(uint32_t* r, uint32_t addr) {
    asm volatile("ldmatrix.sync.aligned.m8n8.x2.shared.b16 {%0,%1}, [%2];"
        : "=r"(r[0]), "=r"(r[1]) : "r"(addr));
}
__device__ __forceinline__ void mma_bf16(float* c, const uint32_t* a, const uint32_t* b) {
    asm volatile(
        "mma.sync.aligned.m16n8k16.row.col.f32.bf16.bf16.f32 "
        "{%0,%1,%2,%3}, {%4,%5,%6,%7}, {%8,%9}, {%0,%1,%2,%3};"
        : "+f"(c[0]), "+f"(c[1]), "+f"(c[2]), "+f"(c[3])
        : "r"(a[0]), "r"(a[1]), "r"(a[2]), "r"(a[3]), "r"(b[0]), "r"(b[1]));
}
__device__ __forceinline__ void split_store(__nv_bfloat16* hi, __nv_bfloat16* lo, int idx, float v) {
    __nv_bfloat16 h = __float2bfloat16(v);
    hi[idx] = h;
    lo[idx] = __float2bfloat16(v - __bfloat162float(h));
}

// ---------------- precompute (3 launches; splits folded in) ----------------
__global__ void k_lam(const float* __restrict__ nu_log,
                      const float* __restrict__ theta_log,
                      const float* __restrict__ gamma_log) {
    int h = threadIdx.x;
    float mod = expf(-expf(nu_log[h]));
    float th  = expf(theta_log[h]);
    g_lam_re[h] = mod * cosf(th);
    g_lam_im[h] = mod * sinf(th);
    g_gam[h]    = expf(gamma_log[h]);
}

__global__ void k_weights(const float* __restrict__ B_re, const float* __restrict__ B_im,
                          const float* __restrict__ C_re, const float* __restrict__ C_im) {
    int idx = blockIdx.x * blockDim.x + threadIdx.x;
    const int NG = 2 * STATE * IN_DIM;
    const int NP = OUT_DIM * STATE;
    if (idx < NG) {
        int c = idx / IN_DIM, j = idx % IN_DIM, h = c >> 1;
        float b = (c & 1) ? B_im[h * IN_DIM + j] : B_re[h * IN_DIM + j];
        float v = b * g_gam[h];
        g_G[idx] = v;
        if (!(c & 1))   // Bn_re row -> Ws split
            split_store(g_Ws_hi, g_Ws_lo, h * IN_DIM + j, v);
    } else if (idx < NG + NP) {
        int t = idx - NG;
        int o = t / STATE, h = t % STATE;
        float cr = C_re[o * STATE + h], ci = C_im[o * STATE + h];
        float lr = g_lam_re[h], li = g_lam_im[h];
        split_store(g_Wy_hi, g_Wy_lo, o * KY + h,        lr * cr - li * ci);
        split_store(g_Wy_hi, g_Wy_lo, o * KY + 512 + h, -(li * cr + lr * ci));
    }
}

// F = D + C_re @ Bn_re - C_im @ Bn_im; split directly into Wy[:,1024:1280]
__global__ void k_F(const float* __restrict__ C_re, const float* __restrict__ C_im,
                    const float* __restrict__ D) {
    __shared__ float sCr[16][16], sCi[16][16], sGr[16][17], sGi[16][17];
    int o0 = blockIdx.y * 16, j0 = blockIdx.x * 16;
    int tx = threadIdx.x, ty = threadIdx.y;
    float acc = 0.f;
    for (int h0 = 0; h0 < STATE; h0 += 16) {
        sCr[ty][tx] = C_re[(o0 + ty) * STATE + h0 + tx];
        sCi[ty][tx] = C_im[(o0 + ty) * STATE + h0 + tx];
        sGr[ty][tx] = g_G[(2 * (h0 + ty)) * IN_DIM + j0 + tx];
        sGi[ty][tx] = g_G[(2 * (h0 + ty) + 1) * IN_DIM + j0 + tx];
        __syncthreads();
#pragma unroll
        for (int k = 0; k < 16; k++)
            acc += sCr[ty][k] * sGr[k][tx] - sCi[ty][k] * sGi[k][tx];
        __syncthreads();
    }
    float fv = D[(o0 + ty) * IN_DIM + j0 + tx] + acc;
    split_store(g_Wy_hi, g_Wy_lo, (o0 + ty) * KY + 1024 + j0 + tx, fv);
}

// ---------------- merged pipelined mma.sync GEMM (bf16 3-term split) ----------------
// BM=128, BN=64, BK=32, 256 thr, 2 CTAs/SM target.
// blocks [0, 1024):    y    = A[x0_re|x0_im|u] @ Wy^T   (K=1280)
// blocks [1024, 3072): s_re = u @ Ws^T + Re(lam*x0)     (K=256, clamped)
#define NY_BLK 1024
#define NS_BLK 2048
// stage byte offsets (A rows 128, W rows 64, row stride 80 B)
#define A_HI_B 0
#define A_LO_B 10240
#define W_HI_B 20480
#define W_LO_B 25600
#define STG_B  30720
#define SMEM_BYTES (2 * STG_B)   // 61440

__global__ __launch_bounds__(256, 2)
void k_merged(const float* __restrict__ u, const float* __restrict__ x0_re,
              const float* __restrict__ x0_im, float* __restrict__ out, long long lim) {
    extern __shared__ __nv_bfloat16 sm[];
    uint32_t sb = smem_u32(sm);

    int bid = blockIdx.x;
    bool is_y = bid < NY_BLK;
    int t_ = is_y ? bid : bid - NY_BLK;
    int m0 = (t_ & 255) * 128;
    int n0 = (t_ >> 8) * 64;
    int KT = is_y ? KY : IN_DIM;
    const __nv_bfloat16* __restrict__ Wh = is_y ? g_Wy_hi : g_Ws_hi;
    const __nv_bfloat16* __restrict__ Wl = is_y ? g_Wy_lo : g_Ws_lo;

    int tid  = threadIdx.x;
    int wid  = tid >> 5;
    int lane = tid & 31;
    int wm = wid & 1;          // 2 warps over M (64 rows)
    int wn = wid >> 1;         // 4 warps over N (16 cols each)

    float acc[4][2][4];
#pragma unroll
    for (int i = 0; i < 4; i++)
#pragma unroll
        for (int j = 0; j < 2; j++)
#pragma unroll
            for (int q = 0; q < 4; q++) acc[i][j][q] = 0.f;

    int lr_  = tid >> 1;        // A loader row (0..127)
    int half = tid & 1;         // k-half (16 elems)
    int wr   = tid >> 2;        // W loader row (0..63)
    int wq   = tid & 3;         // W k-quarter (8 elems)
    uint32_t abase = (uint32_t)lr_ * 80 + half * 32;
    uint32_t wbase = (uint32_t)wr * 80 + wq * 16;

    auto a_ptr = [&](int k0) -> const float* {
        const float* Ag; int astr;
        if (is_y) {
            if (k0 < 512)       { Ag = x0_re + k0;          astr = STATE; }
            else if (k0 < 1024) { Ag = x0_im + (k0 - 512);  astr = STATE; }
            else                { Ag = u + (k0 - 1024);     astr = IN_DIM; }
        } else { Ag = u + k0; astr = IN_DIM; }
        return Ag + (size_t)(m0 + lr_) * astr + half * 16;
    };

    float4 pv0, pv1, pv2, pv3;
    auto load_a = [&](int k0) {
        const float* p = a_ptr(k0);
        pv0 = *(const float4*)(p);
        pv1 = *(const float4*)(p + 4);
        pv2 = *(const float4*)(p + 8);
        pv3 = *(const float4*)(p + 12);
    };
    auto issue_w = [&](int k0, uint32_t stgB) {
        size_t off = (size_t)(n0 + wr) * KT + k0 + wq * 8;
        cp16(sb + stgB + W_HI_B + wbase, Wh + off);
        cp16(sb + stgB + W_LO_B + wbase, Wl + off);
    };
    auto store_a = [&](uint32_t stgB) {
        float xs[16] = {pv0.x, pv0.y, pv0.z, pv0.w, pv1.x, pv1.y, pv1.z, pv1.w,
                        pv2.x, pv2.y, pv2.z, pv2.w, pv3.x, pv3.y, pv3.z, pv3.w};
        uint32_t hu[8], lu[8];
#pragma unroll
        for (int q = 0; q < 8; q++) {
            __nv_bfloat16 h0 = __float2bfloat16(xs[2 * q]);
            __nv_bfloat16 h1 = __float2bfloat16(xs[2 * q + 1]);
            uint32_t l0 = __bfloat16_as_ushort(__float2bfloat16(xs[2 * q]     - __bfloat162float(h0)));
            uint32_t l1 = __bfloat16_as_ushort(__float2bfloat16(xs[2 * q + 1] - __bfloat162float(h1)));
            hu[q] = (uint32_t)__bfloat16_as_ushort(h0) | ((uint32_t)__bfloat16_as_ushort(h1) << 16);
            lu[q] = l0 | (l1 << 16);
        }
        uint32_t b = sb + stgB + abase;
        sts128(b + A_HI_B,      hu[0], hu[1], hu[2], hu[3]);
        sts128(b + A_HI_B + 16, hu[4], hu[5], hu[6], hu[7]);
        sts128(b + A_LO_B,      lu[0], lu[1], lu[2], lu[3]);
        sts128(b + A_LO_B + 16, lu[4], lu[5], lu[6], lu[7]);
    };

    // prologue
    load_a(0);
    issue_w(0, 0);
    store_a(0);
    cp_commit_wait();
    __syncthreads();

#pragma unroll 1
    for (int k0 = 0; k0 < KT; k0 += 32) {
        uint32_t cur = (uint32_t)((k0 >> 5) & 1) * STG_B;
        uint32_t nxt = STG_B - cur;
        bool more = (k0 + 32) < KT;
        if (more) { load_a(k0 + 32); issue_w(k0 + 32, nxt); }

        uint32_t sc = sb + cur;
#pragma unroll
        for (int ks = 0; ks < 2; ks++) {
            uint32_t ah[4][4], al[4][4], bh[2][2], bl[2][2];
            uint32_t acol = ks * 32 + (lane >> 4) * 16;
#pragma unroll
            for (int mt = 0; mt < 4; mt++) {
                uint32_t r = wm * 64 + mt * 16 + (lane & 15);
                uint32_t ad = r * 80 + acol;
                ldm_x4(ah[mt], sc + A_HI_B + ad);
                ldm_x4(al[mt], sc + A_LO_B + ad);
            }
            uint32_t bcol = ks * 32 + ((lane >> 3) & 1) * 16;
#pragma unroll
            for (int nt = 0; nt < 2; nt++) {
                uint32_t n = wn * 16 + nt * 8 + (lane & 7);
                uint32_t bd = n * 80 + bcol;
                ldm_x2(bh[nt], sc + W_HI_B + bd);
                ldm_x2(bl[nt], sc + W_LO_B + bd);
            }
#pragma unroll
            for (int mt = 0; mt < 4; mt++)
#pragma unroll
                for (int nt = 0; nt < 2; nt++) {
                    mma_bf16(acc[mt][nt], ah[mt], bh[nt]);
                    mma_bf16(acc[mt][nt], ah[mt], bl[nt]);
                    mma_bf16(acc[mt][nt], al[mt], bh[nt]);
                }
        }

        if (more) { store_a(nxt); cp_commit_wait(); }
        __syncthreads();
    }

    // epilogue
    int rbase = m0 + wm * 64 + (lane >> 2);
    int cbase = n0 + wn * 16 + 2 * (lane & 3);
#pragma unroll
    for (int mt = 0; mt < 4; mt++) {
#pragma unroll
        for (int nt = 0; nt < 2; nt++) {
            int col = cbase + nt * 8;
#pragma unroll
            for (int hrow = 0; hrow < 2; hrow++) {
                int row = rbase + mt * 16 + hrow * 8;
                float v0 = acc[mt][nt][2 * hrow];
                float v1 = acc[mt][nt][2 * hrow + 1];
                if (is_y) {
                    *(float2*)(out + (size_t)row * OUT_DIM + col) = make_float2(v0, v1);
                } else {
                    long long idx = (long long)NSEQ * OUT_DIM + (long long)row * STATE + col;
                    if (idx + 1 < lim) {
                        float2 lr2 = *(const float2*)&g_lam_re[col];
                        float2 li2 = *(const float2*)&g_lam_im[col];
                        float2 xr  = *(const float2*)&x0_re[(size_t)row * STATE + col];
                        float2 xi  = *(const float2*)&x0_im[(size_t)row * STATE + col];
                        float2 o2;
                        o2.x = lr2.x * xr.x - li2.x * xi.x + v0;
                        o2.y = lr2.y * xr.y - li2.y * xi.y + v1;
                        *(float2*)(out + idx) = o2;
                    }
                }
            }
        }
    }
}

// ---------------- legacy fp32 GEMM (interleaved-c64 state fallback only) ----------------
__global__ __launch_bounds__(256)
void k_gemm_c64(const float* __restrict__ A0, int K0,
                const float* __restrict__ x0_re, const float* __restrict__ x0_im,
                float* __restrict__ out, long long lim) {
    const int BM = 128, BN = 64, BK = 16;
    __shared__ float As[BK][BM + 4];
    __shared__ float Bs[BK][BN + 4];
    int tid = threadIdx.x;
    int m0 = blockIdx.x * BM;
    int n0 = blockIdx.y * BN;
    int tx = tid & 15, ty = tid >> 4;
    float acc[8][4];
#pragma unroll
    for (int i = 0; i < 8; i++)
#pragma unroll
        for (int j = 0; j < 4; j++) acc[i][j] = 0.f;
#pragma unroll 1
    for (int k0 = 0; k0 < K0; k0 += BK) {
#pragma unroll
        for (int l = 0; l < 2; l++) {
            int f = tid + l * 256;
            int r = f >> 2, kk4 = (f & 3) * 4;
            float4 v = *(const float4*)&A0[(size_t)(m0 + r) * K0 + k0 + kk4];
            As[kk4 + 0][r] = v.x; As[kk4 + 1][r] = v.y;
            As[kk4 + 2][r] = v.z; As[kk4 + 3][r] = v.w;
        }
        {
            int n = tid >> 2, kk4 = (tid & 3) * 4;
            float4 v = *(const float4*)&g_G[(size_t)(n0 + n) * K0 + k0 + kk4];
            Bs[kk4 + 0][n] = v.x; Bs[kk4 + 1][n] = v.y;
            Bs[kk4 + 2][n] = v.z; Bs[kk4 + 3][n] = v.w;
        }
        __syncthreads();
#pragma unroll
        for (int kk = 0; kk < BK; kk++) {
            float4 b  = *(const float4*)&Bs[kk][tx * 4];
            float4 a0 = *(const float4*)&As[kk][ty * 8];
            float4 a1 = *(const float4*)&As[kk][ty * 8 + 4];
            float av[8] = {a0.x, a0.y, a0.z, a0.w, a1.x, a1.y, a1.z, a1.w};
            float bv[4] = {b.x, b.y, b.z, b.w};
#pragma unroll
            for (int i = 0; i < 8; i++)
#pragma unroll
                for (int j = 0; j < 4; j++) acc[i][j] += av[i] * bv[j];
        }
        __syncthreads();
    }
    int c0 = n0 + tx * 4;
    int h0 = c0 >> 1;
    float lr0 = g_lam_re[h0],     li0 = g_lam_im[h0];
    float lr1 = g_lam_re[h0 + 1], li1 = g_lam_im[h0 + 1];
#pragma unroll
    for (int i = 0; i < 8; i++) {
        int row = m0 + ty * 8 + i;
        long long idx = (long long)row * (2 * STATE) + c0;
        if (idx + 3 < lim) {
            float xr0 = x0_re[(size_t)row * STATE + h0];
            float xi0 = x0_im[(size_t)row * STATE + h0];
            float xr1 = x0_re[(size_t)row * STATE + h0 + 1];
            float xi1 = x0_im[(size_t)row * STATE + h0 + 1];
            float4 v;
            v.x = lr0 * xr0 - li0 * xi0 + acc[i][0];
            v.y = lr0 * xi0 + li0 * xr0 + acc[i][1];
            v.z = lr1 * xr1 - li1 * xi1 + acc[i][2];
            v.w = lr1 * xi1 + li1 * xr1 + acc[i][3];
            *(float4*)&out[idx] = v;
        }
    }
}

// ---------------- launch ----------------
extern "C" void kernel_launch(void* const* d_in, const int* in_sizes, int n_in,
                              void* d_out, int out_size) {
    const long long expect[11] = {
        (long long)NSEQ * IN_DIM, (long long)NSEQ * STATE, (long long)NSEQ * STATE,
        STATE, STATE, STATE,
        (long long)STATE * IN_DIM, (long long)STATE * IN_DIM,
        (long long)OUT_DIM * STATE, (long long)OUT_DIM * STATE,
        (long long)OUT_DIM * IN_DIM
    };
    const float* ptr[11];
    bool used[32] = {false};
    for (int e = 0; e < 11; e++) {
        ptr[e] = nullptr;
        for (int i = 0; i < n_in; i++) {
            if (!used[i] && (long long)in_sizes[i] == expect[e]) {
                ptr[e] = (const float*)d_in[i];
                used[i] = true;
                break;
            }
        }
        if (!ptr[e]) ptr[e] = (const float*)d_in[e < n_in ? e : 0];
    }
    const float* u         = ptr[0];
    const float* x0_re     = ptr[1];
    const float* x0_im     = ptr[2];
    const float* nu_log    = ptr[3];
    const float* theta_log = ptr[4];
    const float* gamma_log = ptr[5];
    const float* B_re      = ptr[6];
    const float* B_im      = ptr[7];
    const float* C_re      = ptr[8];
    const float* C_im      = ptr[9];
    const float* D         = ptr[10];
    float* out = (float*)d_out;

    static int attr_done = 0;
    if (!attr_done) {
        cudaFuncSetAttribute(k_merged, cudaFuncAttributeMaxDynamicSharedMemorySize, SMEM_BYTES);
        attr_done = 1;
    }

    k_lam<<<1, STATE>>>(nu_log, theta_log, gamma_log);
    int tot = 2 * STATE * IN_DIM + OUT_DIM * STATE;
    k_weights<<<(tot + 255) / 256, 256>>>(B_re, B_im, C_re, C_im);
    k_F<<<dim3(IN_DIM / 16, OUT_DIM / 16), dim3(16, 16)>>>(C_re, C_im, D);

    const long long Y_ELEMS      = (long long)NSEQ * OUT_DIM;   //  8,388,608
    const long long ST_C64_ELEMS = (long long)NSEQ * 2 * STATE; // 33,554,432
    const long long ST_RE_ELEMS  = (long long)NSEQ * STATE;     // 16,777,216
    long long cap = (long long)out_size;
    if (cap == Y_ELEMS / 2 + ST_C64_ELEMS / 2) cap *= 2;        // c64-counted case
    long long rem = cap - Y_ELEMS;

    if (rem >= ST_C64_ELEMS) {
        // y blocks only + legacy interleaved-c64 state
        k_merged<<<NY_BLK, 256, SMEM_BYTES>>>(u, x0_re, x0_im, out, cap);
        k_gemm_c64<<<dim3(NSEQ / 128, (2 * STATE) / 64), 256>>>(
            u, IN_DIM, x0_re, x0_im, out + Y_ELEMS, rem);
    } else {
        // confirmed path: y + real-plane state in ONE launch
        k_merged<<<NY_BLK + NS_BLK, 256, SMEM_BYTES>>>(u, x0_re, x0_im, out, cap);
    }
}

// round 11
// speedup vs baseline: 1.9498x; 1.0540x over previous
#include <cuda_runtime.h>
#include <cuda_bf16.h>
#include <math.h>
#include <stdint.h>

#define IN_DIM   256
#define STATE    512
#define OUT_DIM  256
#define NSEQ     32768
#define KY       1280   // x0_re(512) | x0_im(512) | u(256)

// ---------------- device scratch (no allocation allowed), 16B-aligned ----------------
__device__ __align__(16) float g_lam_re[STATE];
__device__ __align__(16) float g_lam_im[STATE];
__device__ __align__(16) float g_gam[STATE];
__device__ __align__(16) float g_G[2 * STATE * IN_DIM];  // [1024,256] fp32 (k_F + c64 fallback)
// bf16 hi/lo split weights (ONLY referenced from device code — host shadow address invalid on ATS)
__device__ __align__(16) __nv_bfloat16 g_Wy_hi[OUT_DIM * KY];
__device__ __align__(16) __nv_bfloat16 g_Wy_lo[OUT_DIM * KY];
__device__ __align__(16) __nv_bfloat16 g_Ws_hi[STATE * IN_DIM];
__device__ __align__(16) __nv_bfloat16 g_Ws_lo[STATE * IN_DIM];

// ---------------- PTX helpers (sm_80-era; legal on compute_103) ----------------
__device__ __forceinline__ uint32_t smem_u32(const void* p) {
    uint32_t a;
    asm("{ .reg .u64 t; cvta.to.shared.u64 t, %1; cvt.u32.u64 %0, t; }" : "=r"(a) : "l"(p));
    return a;
}
__device__ __forceinline__ void sts128(uint32_t a, uint32_t x, uint32_t y, uint32_t z, uint32_t w) {
    asm volatile("st.shared.v4.b32 [%0], {%1,%2,%3,%4};" :: "r"(a), "r"(x), "r"(y), "r"(z), "r"(w) : "memory");
}
__device__ __forceinline__ void cp16(uint32_t dst, const void* src) {
    asm volatile("cp.async.cg.shared.global [%0], [%1], 16;" :: "r"(dst), "l"(src) : "memory");
}
__device__ __forceinline__ void cp_commit_wait() {
    asm volatile("cp.async.commit_group;" ::: "memory");
    asm volatile("cp.async.wait_group 0;" ::: "memory");
}
__device__ __forceinline__ void ldm_x4(uint32_t* r, uint32_t addr) {
    asm volatile("ldmatrix.sync.aligned.m8n8.x4.shared.b16 {%0,%1,%2,%3}, [%4];"
        : "=r"(r[0]), "=r"(r[1]), "=r"(r[2]), "=r"(r[3]) : "r"(addr));
}
__device__ __forceinline__ void mma_bf16(float* c, const uint32_t* a, const uint32_t* b) {
    asm volatile(
        "mma.sync.aligned.m16n8k16.row.col.f32.bf16.bf16.f32 "
        "{%0,%1,%2,%3}, {%4,%5,%6,%7}, {%8,%9}, {%0,%1,%2,%3};"
        : "+f"(c[0]), "+f"(c[1]), "+f"(c[2]), "+f"(c[3])
        : "r"(a[0]), "r"(a[1]), "r"(a[2]), "r"(a[3]), "r"(b[0]), "r"(b[1]));
}
__device__ __forceinline__ void split_store(__nv_bfloat16* hi, __nv_bfloat16* lo, int idx, float v) {
    __nv_bfloat16 h = __float2bfloat16(v);
    hi[idx] = h;
    lo[idx] = __float2bfloat16(v - __bfloat162float(h));
}

// ---------------- precompute (3 launches; splits folded in) ----------------
__global__ void k_lam(const float* __restrict__ nu_log,
                      const float* __restrict__ theta_log,
                      const float* __restrict__ gamma_log) {
    int h = threadIdx.x;
    float mod = expf(-expf(nu_log[h]));
    float th  = expf(theta_log[h]);
    g_lam_re[h] = mod * cosf(th);
    g_lam_im[h] = mod * sinf(th);
    g_gam[h]    = expf(gamma_log[h]);
}

__global__ void k_weights(const float* __restrict__ B_re, const float* __restrict__ B_im,
                          const float* __restrict__ C_re, const float* __restrict__ C_im) {
    int idx = blockIdx.x * blockDim.x + threadIdx.x;
    const int NG = 2 * STATE * IN_DIM;
    const int NP = OUT_DIM * STATE;
    if (idx < NG) {
        int c = idx / IN_DIM, j = idx % IN_DIM, h = c >> 1;
        float b = (c & 1) ? B_im[h * IN_DIM + j] : B_re[h * IN_DIM + j];
        float v = b * g_gam[h];
        g_G[idx] = v;
        if (!(c & 1))
            split_store(g_Ws_hi, g_Ws_lo, h * IN_DIM + j, v);
    } else if (idx < NG + NP) {
        int t = idx - NG;
        int o = t / STATE, h = t % STATE;
        float cr = C_re[o * STATE + h], ci = C_im[o * STATE + h];
        float lr = g_lam_re[h], li = g_lam_im[h];
        split_store(g_Wy_hi, g_Wy_lo, o * KY + h,        lr * cr - li * ci);
        split_store(g_Wy_hi, g_Wy_lo, o * KY + 512 + h, -(li * cr + lr * ci));
    }
}

__global__ void k_F(const float* __restrict__ C_re, const float* __restrict__ C_im,
                    const float* __restrict__ D) {
    __shared__ float sCr[16][16], sCi[16][16], sGr[16][17], sGi[16][17];
    int o0 = blockIdx.y * 16, j0 = blockIdx.x * 16;
    int tx = threadIdx.x, ty = threadIdx.y;
    float acc = 0.f;
    for (int h0 = 0; h0 < STATE; h0 += 16) {
        sCr[ty][tx] = C_re[(o0 + ty) * STATE + h0 + tx];
        sCi[ty][tx] = C_im[(o0 + ty) * STATE + h0 + tx];
        sGr[ty][tx] = g_G[(2 * (h0 + ty)) * IN_DIM + j0 + tx];
        sGi[ty][tx] = g_G[(2 * (h0 + ty) + 1) * IN_DIM + j0 + tx];
        __syncthreads();
#pragma unroll
        for (int k = 0; k < 16; k++)
            acc += sCr[ty][k] * sGr[k][tx] - sCi[ty][k] * sGi[k][tx];
        __syncthreads();
    }
    float fv = D[(o0 + ty) * IN_DIM + j0 + tx] + acc;
    split_store(g_Wy_hi, g_Wy_lo, (o0 + ty) * KY + 1024 + j0 + tx, fv);
}

// ---------------- merged pipelined mma.sync GEMM (bf16 3-term split) ----------------
// BM=128, BN=64, BK=32, 256 thr, 2 CTAs/SM.
// Block map is N-INNER so consecutive (co-resident) CTAs share A rows via L2:
//   y blocks   [0, 1024):    m = t>>2, n = t&3   (K=1280)
//   s blocks   [1024, 3072): m = t>>3, n = t&7   (K=256, epilogue Re(lam*x0), clamped)
// Warp layout: 4 warps over M (32 rows), 2 warps over N (32 cols) -> mt=2, nt=4.
#define NY_BLK 1024
#define NS_BLK 2048
#define A_HI_B 0
#define A_LO_B 10240
#define W_HI_B 20480
#define W_LO_B 25600
#define STG_B  30720
#define SMEM_BYTES (2 * STG_B)   // 61440

__global__ __launch_bounds__(256, 2)
void k_merged(const float* __restrict__ u, const float* __restrict__ x0_re,
              const float* __restrict__ x0_im, float* __restrict__ out, long long lim) {
    extern __shared__ __nv_bfloat16 sm[];
    uint32_t sb = smem_u32(sm);

    int bid = blockIdx.x;
    bool is_y = bid < NY_BLK;
    int t_ = is_y ? bid : bid - NY_BLK;
    int m0, n0;
    if (is_y) { m0 = (t_ >> 2) * 128; n0 = (t_ & 3) * 64; }
    else      { m0 = (t_ >> 3) * 128; n0 = (t_ & 7) * 64; }
    int KT = is_y ? KY : IN_DIM;
    const __nv_bfloat16* __restrict__ Wh = is_y ? g_Wy_hi : g_Ws_hi;
    const __nv_bfloat16* __restrict__ Wl = is_y ? g_Wy_lo : g_Ws_lo;

    int tid  = threadIdx.x;
    int wid  = tid >> 5;
    int lane = tid & 31;
    int wm = wid & 3;          // 4 warps over M (32 rows each)
    int wn = wid >> 2;         // 2 warps over N (32 cols each)

    float acc[2][4][4];
#pragma unroll
    for (int i = 0; i < 2; i++)
#pragma unroll
        for (int j = 0; j < 4; j++)
#pragma unroll
            for (int q = 0; q < 4; q++) acc[i][j][q] = 0.f;

    int lr_  = tid >> 1;        // A loader row (0..127)
    int half = tid & 1;         // k-half (16 elems)
    int wr   = tid >> 2;        // W loader row (0..63)
    int wq   = tid & 3;         // W k-quarter (8 elems)
    uint32_t abase = (uint32_t)lr_ * 80 + half * 32;
    uint32_t wbase = (uint32_t)wr * 80 + wq * 16;

    auto a_ptr = [&](int k0) -> const float* {
        const float* Ag; int astr;
        if (is_y) {
            if (k0 < 512)       { Ag = x0_re + k0;          astr = STATE; }
            else if (k0 < 1024) { Ag = x0_im + (k0 - 512);  astr = STATE; }
            else                { Ag = u + (k0 - 1024);     astr = IN_DIM; }
        } else { Ag = u + k0; astr = IN_DIM; }
        return Ag + (size_t)(m0 + lr_) * astr + half * 16;
    };

    float4 pv0, pv1, pv2, pv3;
    auto load_a = [&](int k0) {
        const float* p = a_ptr(k0);
        pv0 = *(const float4*)(p);
        pv1 = *(const float4*)(p + 4);
        pv2 = *(const float4*)(p + 8);
        pv3 = *(const float4*)(p + 12);
    };
    auto issue_w = [&](int k0, uint32_t stgB) {
        size_t off = (size_t)(n0 + wr) * KT + k0 + wq * 8;
        cp16(sb + stgB + W_HI_B + wbase, Wh + off);
        cp16(sb + stgB + W_LO_B + wbase, Wl + off);
    };
    auto store_a = [&](uint32_t stgB) {
        float xs[16] = {pv0.x, pv0.y, pv0.z, pv0.w, pv1.x, pv1.y, pv1.z, pv1.w,
                        pv2.x, pv2.y, pv2.z, pv2.w, pv3.x, pv3.y, pv3.z, pv3.w};
        uint32_t hu[8], lu[8];
#pragma unroll
        for (int q = 0; q < 8; q++) {
            __nv_bfloat16 h0 = __float2bfloat16(xs[2 * q]);
            __nv_bfloat16 h1 = __float2bfloat16(xs[2 * q + 1]);
            uint32_t l0 = __bfloat16_as_ushort(__float2bfloat16(xs[2 * q]     - __bfloat162float(h0)));
            uint32_t l1 = __bfloat16_as_ushort(__float2bfloat16(xs[2 * q + 1] - __bfloat162float(h1)));
            hu[q] = (uint32_t)__bfloat16_as_ushort(h0) | ((uint32_t)__bfloat16_as_ushort(h1) << 16);
            lu[q] = l0 | (l1 << 16);
        }
        uint32_t b = sb + stgB + abase;
        sts128(b + A_HI_B,      hu[0], hu[1], hu[2], hu[3]);
        sts128(b + A_HI_B + 16, hu[4], hu[5], hu[6], hu[7]);
        sts128(b + A_LO_B,      lu[0], lu[1], lu[2], lu[3]);
        sts128(b + A_LO_B + 16, lu[4], lu[5], lu[6], lu[7]);
    };

    // prologue
    load_a(0);
    issue_w(0, 0);
    store_a(0);
    cp_commit_wait();
    __syncthreads();

#pragma unroll 1
    for (int k0 = 0; k0 < KT; k0 += 32) {
        uint32_t cur = (uint32_t)((k0 >> 5) & 1) * STG_B;
        uint32_t nxt = STG_B - cur;
        bool more = (k0 + 32) < KT;
        if (more) { load_a(k0 + 32); issue_w(k0 + 32, nxt); }

        uint32_t sc = sb + cur;
#pragma unroll
        for (int ks = 0; ks < 2; ks++) {
            uint32_t ah[2][4], al[2][4], bh[4][2], bl[4][2];
            // A fragments: 16x16 tiles, rows wm*32 + mt*16
            uint32_t acol = ks * 32 + (lane >> 4) * 16;
#pragma unroll
            for (int mt = 0; mt < 2; mt++) {
                uint32_t r = wm * 32 + mt * 16 + (lane & 15);
                uint32_t ad = r * 80 + acol;
                ldm_x4(ah[mt], sc + A_HI_B + ad);
                ldm_x4(al[mt], sc + A_LO_B + ad);
            }
            // W fragments: paired x4 — one call covers two n-subtiles (16 rows x 16 k)
            uint32_t brow_lo = (uint32_t)((lane >> 4) << 3) + (lane & 7);
            uint32_t bcol    = ks * 32 + ((lane >> 3) & 1) * 16;
#pragma unroll
            for (int p = 0; p < 2; p++) {
                uint32_t n = wn * 32 + p * 16 + brow_lo;
                uint32_t bd = n * 80 + bcol;
                uint32_t th[4], tl[4];
                ldm_x4(th, sc + W_HI_B + bd);
                ldm_x4(tl, sc + W_LO_B + bd);
                bh[2*p][0] = th[0]; bh[2*p][1] = th[1]; bh[2*p+1][0] = th[2]; bh[2*p+1][1] = th[3];
                bl[2*p][0] = tl[0]; bl[2*p][1] = tl[1]; bl[2*p+1][0] = tl[2]; bl[2*p+1][1] = tl[3];
            }
#pragma unroll
            for (int mt = 0; mt < 2; mt++)
#pragma unroll
                for (int nt = 0; nt < 4; nt++) {
                    mma_bf16(acc[mt][nt], ah[mt], bh[nt]);
                    mma_bf16(acc[mt][nt], ah[mt], bl[nt]);
                    mma_bf16(acc[mt][nt], al[mt], bh[nt]);
                }
        }

        if (more) { store_a(nxt); cp_commit_wait(); }
        __syncthreads();
    }

    // epilogue
    int rbase = m0 + wm * 32 + (lane >> 2);
    int cbase = n0 + wn * 32 + 2 * (lane & 3);
#pragma unroll
    for (int mt = 0; mt < 2; mt++) {
#pragma unroll
        for (int nt = 0; nt < 4; nt++) {
            int col = cbase + nt * 8;
#pragma unroll
            for (int hrow = 0; hrow < 2; hrow++) {
                int row = rbase + mt * 16 + hrow * 8;
                float v0 = acc[mt][nt][2 * hrow];
                float v1 = acc[mt][nt][2 * hrow + 1];
                if (is_y) {
                    *(float2*)(out + (size_t)row * OUT_DIM + col) = make_float2(v0, v1);
                } else {
                    long long idx = (long long)NSEQ * OUT_DIM + (long long)row * STATE + col;
                    if (idx + 1 < lim) {
                        float2 lr2 = *(const float2*)&g_lam_re[col];
                        float2 li2 = *(const float2*)&g_lam_im[col];
                        float2 xr  = *(const float2*)&x0_re[(size_t)row * STATE + col];
                        float2 xi  = *(const float2*)&x0_im[(size_t)row * STATE + col];
                        float2 o2;
                        o2.x = lr2.x * xr.x - li2.x * xi.x + v0;
                        o2.y = lr2.y * xr.y - li2.y * xi.y + v1;
                        *(float2*)(out + idx) = o2;
                    }
                }
            }
        }
    }
}

// ---------------- legacy fp32 GEMM (interleaved-c64 state fallback only) ----------------
__global__ __launch_bounds__(256)
void k_gemm_c64(const float* __restrict__ A0, int K0,
                const float* __restrict__ x0_re, const float* __restrict__ x0_im,
                float* __restrict__ out, long long lim) {
    const int BM = 128, BN = 64, BK = 16;
    __shared__ float As[BK][BM + 4];
    __shared__ float Bs[BK][BN + 4];
    int tid = threadIdx.x;
    int m0 = blockIdx.x * BM;
    int n0 = blockIdx.y * BN;
    int tx = tid & 15, ty = tid >> 4;
    float acc[8][4];
#pragma unroll
    for (int i = 0; i < 8; i++)
#pragma unroll
        for (int j = 0; j < 4; j++) acc[i][j] = 0.f;
#pragma unroll 1
    for (int k0 = 0; k0 < K0; k0 += BK) {
#pragma unroll
        for (int l = 0; l < 2; l++) {
            int f = tid + l * 256;
            int r = f >> 2, kk4 = (f & 3) * 4;
            float4 v = *(const float4*)&A0[(size_t)(m0 + r) * K0 + k0 + kk4];
            As[kk4 + 0][r] = v.x; As[kk4 + 1][r] = v.y;
            As[kk4 + 2][r] = v.z; As[kk4 + 3][r] = v.w;
        }
        {
            int n = tid >> 2, kk4 = (tid & 3) * 4;
            float4 v = *(const float4*)&g_G[(size_t)(n0 + n) * K0 + k0 + kk4];
            Bs[kk4 + 0][n] = v.x; Bs[kk4 + 1][n] = v.y;
            Bs[kk4 + 2][n] = v.z; Bs[kk4 + 3][n] = v.w;
        }
        __syncthreads();
#pragma unroll
        for (int kk = 0; kk < BK; kk++) {
            float4 b  = *(const float4*)&Bs[kk][tx * 4];
            float4 a0 = *(const float4*)&As[kk][ty * 8];
            float4 a1 = *(const float4*)&As[kk][ty * 8 + 4];
            float av[8] = {a0.x, a0.y, a0.z, a0.w, a1.x, a1.y, a1.z, a1.w};
            float bv[4] = {b.x, b.y, b.z, b.w};
#pragma unroll
            for (int i = 0; i < 8; i++)
#pragma unroll
                for (int j = 0; j < 4; j++) acc[i][j] += av[i] * bv[j];
        }
        __syncthreads();
    }
    int c0 = n0 + tx * 4;
    int h0 = c0 >> 1;
    float lr0 = g_lam_re[h0],     li0 = g_lam_im[h0];
    float lr1 = g_lam_re[h0 + 1], li1 = g_lam_im[h0 + 1];
#pragma unroll
    for (int i = 0; i < 8; i++) {
        int row = m0 + ty * 8 + i;
        long long idx = (long long)row * (2 * STATE) + c0;
        if (idx + 3 < lim) {
            float xr0 = x0_re[(size_t)row * STATE + h0];
            float xi0 = x0_im[(size_t)row * STATE + h0];
            float xr1 = x0_re[(size_t)row * STATE + h0 + 1];
            float xi1 = x0_im[(size_t)row * STATE + h0 + 1];
            float4 v;
            v.x = lr0 * xr0 - li0 * xi0 + acc[i][0];
            v.y = lr0 * xi0 + li0 * xr0 + acc[i][1];
            v.z = lr1 * xr1 - li1 * xi1 + acc[i][2];
            v.w = lr1 * xi1 + li1 * xr1 + acc[i][3];
            *(float4*)&out[idx] = v;
        }
    }
}

// ---------------- launch ----------------
extern "C" void kernel_launch(void* const* d_in, const int* in_sizes, int n_in,
                              void* d_out, int out_size) {
    const long long expect[11] = {
        (long long)NSEQ * IN_DIM, (long long)NSEQ * STATE, (long long)NSEQ * STATE,
        STATE, STATE, STATE,
        (long long)STATE * IN_DIM, (long long)STATE * IN_DIM,
        (long long)OUT_DIM * STATE, (long long)OUT_DIM * STATE,
        (long long)OUT_DIM * IN_DIM
    };
    const float* ptr[11];
    bool used[32] = {false};
    for (int e = 0; e < 11; e++) {
        ptr[e] = nullptr;
        for (int i = 0; i < n_in; i++) {
            if (!used[i] && (long long)in_sizes[i] == expect[e]) {
                ptr[e] = (const float*)d_in[i];
                used[i] = true;
                break;
            }
        }
        if (!ptr[e]) ptr[e] = (const float*)d_in[e < n_in ? e : 0];
    }
    const float* u         = ptr[0];
    const float* x0_re     = ptr[1];
    const float* x0_im     = ptr[2];
    const float* nu_log    = ptr[3];
    const float* theta_log = ptr[4];
    const float* gamma_log = ptr[5];
    const float* B_re      = ptr[6];
    const float* B_im      = ptr[7];
    const float* C_re      = ptr[8];
    const float* C_im      = ptr[9];
    const float* D         = ptr[10];
    float* out = (float*)d_out;

    static int attr_done = 0;
    if (!attr_done) {
        cudaFuncSetAttribute(k_merged, cudaFuncAttributeMaxDynamicSharedMemorySize, SMEM_BYTES);
        attr_done = 1;
    }

    k_lam<<<1, STATE>>>(nu_log, theta_log, gamma_log);
    int tot = 2 * STATE * IN_DIM + OUT_DIM * STATE;
    k_weights<<<(tot + 255) / 256, 256>>>(B_re, B_im, C_re, C_im);
    k_F<<<dim3(IN_DIM / 16, OUT_DIM / 16), dim3(16, 16)>>>(C_re, C_im, D);

    const long long Y_ELEMS      = (long long)NSEQ * OUT_DIM;   //  8,388,608
    const long long ST_C64_ELEMS = (long long)NSEQ * 2 * STATE; // 33,554,432
    long long cap = (long long)out_size;
    if (cap == Y_ELEMS / 2 + ST_C64_ELEMS / 2) cap *= 2;        // c64-counted case
    long long rem = cap - Y_ELEMS;

    if (rem >= ST_C64_ELEMS) {
        k_merged<<<NY_BLK, 256, SMEM_BYTES>>>(u, x0_re, x0_im, out, cap);
        k_gemm_c64<<<dim3(NSEQ / 128, (2 * STATE) / 64), 256>>>(
            u, IN_DIM, x0_re, x0_im, out + Y_ELEMS, rem);
    } else {
        k_merged<<<NY_BLK + NS_BLK, 256, SMEM_BYTES>>>(u, x0_re, x0_im, out, cap);
    }
}

// round 12
// speedup vs baseline: 2.1771x; 1.1166x over previous
#include <cuda_runtime.h>
#include <cuda_bf16.h>
#include <cuda_fp16.h>
#include <math.h>
#include <stdint.h>

#define IN_DIM   256
#define STATE    512
#define OUT_DIM  256
#define NSEQ     32768
#define KY       1280   // x0_re(512) | x0_im(512) | u(256)

// ---------------- device scratch (no allocation allowed), 16B-aligned ----------------
__device__ __align__(16) float g_lam_re[STATE];
__device__ __align__(16) float g_lam_im[STATE];
__device__ __align__(16) float g_gam[STATE];
__device__ __align__(16) float g_G[2 * STATE * IN_DIM];  // [1024,256] fp32 (k_F + c64 fallback)
// fp16 weights (single precision-level: A is split hi/lo, W quantization dominates error ~2^-11)
// ONLY referenced from device code — host shadow address invalid on ATS.
__device__ __align__(16) __half g_Wy_h[OUT_DIM * KY];     // [256][1280] = [P|Q|F]
__device__ __align__(16) __half g_Ws_h[STATE * IN_DIM];   // [512][256]  = Bn_re

// ---------------- PTX helpers (sm_80-era; legal on compute_103) ----------------
__device__ __forceinline__ uint32_t smem_u32(const void* p) {
    uint32_t a;
    asm("{ .reg .u64 t; cvta.to.shared.u64 t, %1; cvt.u32.u64 %0, t; }" : "=r"(a) : "l"(p));
    return a;
}
__device__ __forceinline__ void sts128(uint32_t a, uint32_t x, uint32_t y, uint32_t z, uint32_t w) {
    asm volatile("st.shared.v4.b32 [%0], {%1,%2,%3,%4};" :: "r"(a), "r"(x), "r"(y), "r"(z), "r"(w) : "memory");
}
__device__ __forceinline__ void cp16(uint32_t dst, const void* src) {
    asm volatile("cp.async.cg.shared.global [%0], [%1], 16;" :: "r"(dst), "l"(src) : "memory");
}
__device__ __forceinline__ void cp_commit_wait() {
    asm volatile("cp.async.commit_group;" ::: "memory");
    asm volatile("cp.async.wait_group 0;" ::: "memory");
}
__device__ __forceinline__ void ldm_x4(uint32_t* r, uint32_t addr) {
    asm volatile("ldmatrix.sync.aligned.m8n8.x4.shared.b16 {%0,%1,%2,%3}, [%4];"
        : "=r"(r[0]), "=r"(r[1]), "=r"(r[2]), "=r"(r[3]) : "r"(addr));
}
__device__ __forceinline__ void mma_f16(float* c, const uint32_t* a, const uint32_t* b) {
    asm volatile(
        "mma.sync.aligned.m16n8k16.row.col.f32.f16.f16.f32 "
        "{%0,%1,%2,%3}, {%4,%5,%6,%7}, {%8,%9}, {%0,%1,%2,%3};"
        : "+f"(c[0]), "+f"(c[1]), "+f"(c[2]), "+f"(c[3])
        : "r"(a[0]), "r"(a[1]), "r"(a[2]), "r"(a[3]), "r"(b[0]), "r"(b[1]));
}

// ---------------- precompute (3 launches) ----------------
__global__ void k_lam(const float* __restrict__ nu_log,
                      const float* __restrict__ theta_log,
                      const float* __restrict__ gamma_log) {
    int h = threadIdx.x;
    float mod = expf(-expf(nu_log[h]));
    float th  = expf(theta_log[h]);
    g_lam_re[h] = mod * cosf(th);
    g_lam_im[h] = mod * sinf(th);
    g_gam[h]    = expf(gamma_log[h]);
}

__global__ void k_weights(const float* __restrict__ B_re, const float* __restrict__ B_im,
                          const float* __restrict__ C_re, const float* __restrict__ C_im) {
    int idx = blockIdx.x * blockDim.x + threadIdx.x;
    const int NG = 2 * STATE * IN_DIM;
    const int NP = OUT_DIM * STATE;
    if (idx < NG) {
        int c = idx / IN_DIM, j = idx % IN_DIM, h = c >> 1;
        float b = (c & 1) ? B_im[h * IN_DIM + j] : B_re[h * IN_DIM + j];
        float v = b * g_gam[h];
        g_G[idx] = v;
        if (!(c & 1))
            g_Ws_h[h * IN_DIM + j] = __float2half(v);
    } else if (idx < NG + NP) {
        int t = idx - NG;
        int o = t / STATE, h = t % STATE;
        float cr = C_re[o * STATE + h], ci = C_im[o * STATE + h];
        float lr = g_lam_re[h], li = g_lam_im[h];
        g_Wy_h[o * KY + h]       = __float2half(lr * cr - li * ci);
        g_Wy_h[o * KY + 512 + h] = __float2half(-(li * cr + lr * ci));
    }
}

__global__ void k_F(const float* __restrict__ C_re, const float* __restrict__ C_im,
                    const float* __restrict__ D) {
    __shared__ float sCr[16][16], sCi[16][16], sGr[16][17], sGi[16][17];
    int o0 = blockIdx.y * 16, j0 = blockIdx.x * 16;
    int tx = threadIdx.x, ty = threadIdx.y;
    float acc = 0.f;
    for (int h0 = 0; h0 < STATE; h0 += 16) {
        sCr[ty][tx] = C_re[(o0 + ty) * STATE + h0 + tx];
        sCi[ty][tx] = C_im[(o0 + ty) * STATE + h0 + tx];
        sGr[ty][tx] = g_G[(2 * (h0 + ty)) * IN_DIM + j0 + tx];
        sGi[ty][tx] = g_G[(2 * (h0 + ty) + 1) * IN_DIM + j0 + tx];
        __syncthreads();
#pragma unroll
        for (int k = 0; k < 16; k++)
            acc += sCr[ty][k] * sGr[k][tx] - sCi[ty][k] * sGi[k][tx];
        __syncthreads();
    }
    float fv = D[(o0 + ty) * IN_DIM + j0 + tx] + acc;
    g_Wy_h[(o0 + ty) * KY + 1024 + j0 + tx] = __float2half(fv);
}

// ---------------- merged pipelined mma.sync GEMM (fp16, 2-term A split) ----------------
// BM=128, BN=64, BK=32, 256 thr, 2 CTAs/SM. N-inner block map (L2 reuse of A).
//   y blocks   [0, 1024):    m = t>>2, n = t&3   (K=1280)
//   s blocks   [1024, 3072): m = t>>3, n = t&7   (K=256, epilogue Re(lam*x0), clamped)
// Warps: 4 over M (32 rows, mt=2), 2 over N (32 cols, nt=4). 2 MMAs per (mt,nt) per k16.
#define NY_BLK 1024
#define NS_BLK 2048
#define A_HI_B 0
#define A_LO_B 10240
#define W_B    20480
#define STG_B  25600
#define SMEM_BYTES (2 * STG_B)   // 51200

__global__ __launch_bounds__(256, 2)
void k_merged(const float* __restrict__ u, const float* __restrict__ x0_re,
              const float* __restrict__ x0_im, float* __restrict__ out, long long lim) {
    extern __shared__ __half sm[];
    uint32_t sb = smem_u32(sm);

    int bid = blockIdx.x;
    bool is_y = bid < NY_BLK;
    int t_ = is_y ? bid : bid - NY_BLK;
    int m0, n0;
    if (is_y) { m0 = (t_ >> 2) * 128; n0 = (t_ & 3) * 64; }
    else      { m0 = (t_ >> 3) * 128; n0 = (t_ & 7) * 64; }
    int KT = is_y ? KY : IN_DIM;
    const __half* __restrict__ Wp = is_y ? g_Wy_h : g_Ws_h;

    int tid  = threadIdx.x;
    int wid  = tid >> 5;
    int lane = tid & 31;
    int wm = wid & 3;
    int wn = wid >> 2;

    float acc[2][4][4];
#pragma unroll
    for (int i = 0; i < 2; i++)
#pragma unroll
        for (int j = 0; j < 4; j++)
#pragma unroll
            for (int q = 0; q < 4; q++) acc[i][j][q] = 0.f;

    int lr_  = tid >> 1;        // A loader row (0..127)
    int half = tid & 1;         // k-half (16 elems)
    int wr   = tid >> 2;        // W loader row (0..63)
    int wq   = tid & 3;         // W k-quarter (8 halves = 16 B)
    uint32_t abase = (uint32_t)lr_ * 80 + half * 32;
    uint32_t wbase = (uint32_t)wr * 80 + wq * 16;

    auto a_ptr = [&](int k0) -> const float* {
        const float* Ag; int astr;
        if (is_y) {
            if (k0 < 512)       { Ag = x0_re + k0;          astr = STATE; }
            else if (k0 < 1024) { Ag = x0_im + (k0 - 512);  astr = STATE; }
            else                { Ag = u + (k0 - 1024);     astr = IN_DIM; }
        } else { Ag = u + k0; astr = IN_DIM; }
        return Ag + (size_t)(m0 + lr_) * astr + half * 16;
    };

    float4 pv0, pv1, pv2, pv3;
    auto load_a = [&](int k0) {
        const float* p = a_ptr(k0);
        pv0 = *(const float4*)(p);
        pv1 = *(const float4*)(p + 4);
        pv2 = *(const float4*)(p + 8);
        pv3 = *(const float4*)(p + 12);
    };
    auto issue_w = [&](int k0, uint32_t stgB) {
        size_t off = (size_t)(n0 + wr) * KT + k0 + wq * 8;
        cp16(sb + stgB + W_B + wbase, Wp + off);
    };
    auto store_a = [&](uint32_t stgB) {
        float xs[16] = {pv0.x, pv0.y, pv0.z, pv0.w, pv1.x, pv1.y, pv1.z, pv1.w,
                        pv2.x, pv2.y, pv2.z, pv2.w, pv3.x, pv3.y, pv3.z, pv3.w};
        uint32_t hu[8], lu[8];
#pragma unroll
        for (int q = 0; q < 8; q++) {
            __half h0 = __float2half(xs[2 * q]);
            __half h1 = __float2half(xs[2 * q + 1]);
            uint32_t l0 = (uint32_t)__half_as_ushort(__float2half(xs[2 * q]     - __half2float(h0)));
            uint32_t l1 = (uint32_t)__half_as_ushort(__float2half(xs[2 * q + 1] - __half2float(h1)));
            hu[q] = (uint32_t)__half_as_ushort(h0) | ((uint32_t)__half_as_ushort(h1) << 16);
            lu[q] = l0 | (l1 << 16);
        }
        uint32_t b = sb + stgB + abase;
        sts128(b + A_HI_B,      hu[0], hu[1], hu[2], hu[3]);
        sts128(b + A_HI_B + 16, hu[4], hu[5], hu[6], hu[7]);
        sts128(b + A_LO_B,      lu[0], lu[1], lu[2], lu[3]);
        sts128(b + A_LO_B + 16, lu[4], lu[5], lu[6], lu[7]);
    };

    // prologue
    load_a(0);
    issue_w(0, 0);
    store_a(0);
    cp_commit_wait();
    __syncthreads();

#pragma unroll 1
    for (int k0 = 0; k0 < KT; k0 += 32) {
        uint32_t cur = (uint32_t)((k0 >> 5) & 1) * STG_B;
        uint32_t nxt = STG_B - cur;
        bool more = (k0 + 32) < KT;
        if (more) { load_a(k0 + 32); issue_w(k0 + 32, nxt); }

        uint32_t sc = sb + cur;
#pragma unroll
        for (int ks = 0; ks < 2; ks++) {
            uint32_t ah[2][4], al[2][4], bh[4][2];
            uint32_t acol = ks * 32 + (lane >> 4) * 16;
#pragma unroll
            for (int mt = 0; mt < 2; mt++) {
                uint32_t r = wm * 32 + mt * 16 + (lane & 15);
                uint32_t ad = r * 80 + acol;
                ldm_x4(ah[mt], sc + A_HI_B + ad);
                ldm_x4(al[mt], sc + A_LO_B + ad);
            }
            // W fragments: paired x4 — one call covers two n-subtiles (16 rows x 16 k)
            uint32_t brow_lo = (uint32_t)((lane >> 4) << 3) + (lane & 7);
            uint32_t bcol    = ks * 32 + ((lane >> 3) & 1) * 16;
#pragma unroll
            for (int p = 0; p < 2; p++) {
                uint32_t n = wn * 32 + p * 16 + brow_lo;
                uint32_t bd = n * 80 + bcol;
                uint32_t th[4];
                ldm_x4(th, sc + W_B + bd);
                bh[2*p][0] = th[0]; bh[2*p][1] = th[1];
                bh[2*p+1][0] = th[2]; bh[2*p+1][1] = th[3];
            }
#pragma unroll
            for (int mt = 0; mt < 2; mt++)
#pragma unroll
                for (int nt = 0; nt < 4; nt++) {
                    mma_f16(acc[mt][nt], ah[mt], bh[nt]);
                    mma_f16(acc[mt][nt], al[mt], bh[nt]);
                }
        }

        if (more) { store_a(nxt); cp_commit_wait(); }
        __syncthreads();
    }

    // epilogue
    int rbase = m0 + wm * 32 + (lane >> 2);
    int cbase = n0 + wn * 32 + 2 * (lane & 3);
#pragma unroll
    for (int mt = 0; mt < 2; mt++) {
#pragma unroll
        for (int nt = 0; nt < 4; nt++) {
            int col = cbase + nt * 8;
#pragma unroll
            for (int hrow = 0; hrow < 2; hrow++) {
                int row = rbase + mt * 16 + hrow * 8;
                float v0 = acc[mt][nt][2 * hrow];
                float v1 = acc[mt][nt][2 * hrow + 1];
                if (is_y) {
                    *(float2*)(out + (size_t)row * OUT_DIM + col) = make_float2(v0, v1);
                } else {
                    long long idx = (long long)NSEQ * OUT_DIM + (long long)row * STATE + col;
                    if (idx + 1 < lim) {
                        float2 lr2 = *(const float2*)&g_lam_re[col];
                        float2 li2 = *(const float2*)&g_lam_im[col];
                        float2 xr  = *(const float2*)&x0_re[(size_t)row * STATE + col];
                        float2 xi  = *(const float2*)&x0_im[(size_t)row * STATE + col];
                        float2 o2;
                        o2.x = lr2.x * xr.x - li2.x * xi.x + v0;
                        o2.y = lr2.y * xr.y - li2.y * xi.y + v1;
                        *(float2*)(out + idx) = o2;
                    }
                }
            }
        }
    }
}

// ---------------- legacy fp32 GEMM (interleaved-c64 state fallback only) ----------------
__global__ __launch_bounds__(256)
void k_gemm_c64(const float* __restrict__ A0, int K0,
                const float* __restrict__ x0_re, const float* __restrict__ x0_im,
                float* __restrict__ out, long long lim) {
    const int BM = 128, BN = 64, BK = 16;
    __shared__ float As[BK][BM + 4];
    __shared__ float Bs[BK][BN + 4];
    int tid = threadIdx.x;
    int m0 = blockIdx.x * BM;
    int n0 = blockIdx.y * BN;
    int tx = tid & 15, ty = tid >> 4;
    float acc[8][4];
#pragma unroll
    for (int i = 0; i < 8; i++)
#pragma unroll
        for (int j = 0; j < 4; j++) acc[i][j] = 0.f;
#pragma unroll 1
    for (int k0 = 0; k0 < K0; k0 += BK) {
#pragma unroll
        for (int l = 0; l < 2; l++) {
            int f = tid + l * 256;
            int r = f >> 2, kk4 = (f & 3) * 4;
            float4 v = *(const float4*)&A0[(size_t)(m0 + r) * K0 + k0 + kk4];
            As[kk4 + 0][r] = v.x; As[kk4 + 1][r] = v.y;
            As[kk4 + 2][r] = v.z; As[kk4 + 3][r] = v.w;
        }
        {
            int n = tid >> 2, kk4 = (tid & 3) * 4;
            float4 v = *(const float4*)&g_G[(size_t)(n0 + n) * K0 + k0 + kk4];
            Bs[kk4 + 0][n] = v.x; Bs[kk4 + 1][n] = v.y;
            Bs[kk4 + 2][n] = v.z; Bs[kk4 + 3][n] = v.w;
        }
        __syncthreads();
#pragma unroll
        for (int kk = 0; kk < BK; kk++) {
            float4 b  = *(const float4*)&Bs[kk][tx * 4];
            float4 a0 = *(const float4*)&As[kk][ty * 8];
            float4 a1 = *(const float4*)&As[kk][ty * 8 + 4];
            float av[8] = {a0.x, a0.y, a0.z, a0.w, a1.x, a1.y, a1.z, a1.w};
            float bv[4] = {b.x, b.y, b.z, b.w};
#pragma unroll
            for (int i = 0; i < 8; i++)
#pragma unroll
                for (int j = 0; j < 4; j++) acc[i][j] += av[i] * bv[j];
        }
        __syncthreads();
    }
    int c0 = n0 + tx * 4;
    int h0 = c0 >> 1;
    float lr0 = g_lam_re[h0],     li0 = g_lam_im[h0];
    float lr1 = g_lam_re[h0 + 1], li1 = g_lam_im[h0 + 1];
#pragma unroll
    for (int i = 0; i < 8; i++) {
        int row = m0 + ty * 8 + i;
        long long idx = (long long)row * (2 * STATE) + c0;
        if (idx + 3 < lim) {
            float xr0 = x0_re[(size_t)row * STATE + h0];
            float xi0 = x0_im[(size_t)row * STATE + h0];
            float xr1 = x0_re[(size_t)row * STATE + h0 + 1];
            float xi1 = x0_im[(size_t)row * STATE + h0 + 1];
            float4 v;
            v.x = lr0 * xr0 - li0 * xi0 + acc[i][0];
            v.y = lr0 * xi0 + li0 * xr0 + acc[i][1];
            v.z = lr1 * xr1 - li1 * xi1 + acc[i][2];
            v.w = lr1 * xi1 + li1 * xr1 + acc[i][3];
            *(float4*)&out[idx] = v;
        }
    }
}

// ---------------- launch ----------------
extern "C" void kernel_launch(void* const* d_in, const int* in_sizes, int n_in,
                              void* d_out, int out_size) {
    const long long expect[11] = {
        (long long)NSEQ * IN_DIM, (long long)NSEQ * STATE, (long long)NSEQ * STATE,
        STATE, STATE, STATE,
        (long long)STATE * IN_DIM, (long long)STATE * IN_DIM,
        (long long)OUT_DIM * STATE, (long long)OUT_DIM * STATE,
        (long long)OUT_DIM * IN_DIM
    };
    const float* ptr[11];
    bool used[32] = {false};
    for (int e = 0; e < 11; e++) {
        ptr[e] = nullptr;
        for (int i = 0; i < n_in; i++) {
            if (!used[i] && (long long)in_sizes[i] == expect[e]) {
                ptr[e] = (const float*)d_in[i];
                used[i] = true;
                break;
            }
        }
        if (!ptr[e]) ptr[e] = (const float*)d_in[e < n_in ? e : 0];
    }
    const float* u         = ptr[0];
    const float* x0_re     = ptr[1];
    const float* x0_im     = ptr[2];
    const float* nu_log    = ptr[3];
    const float* theta_log = ptr[4];
    const float* gamma_log = ptr[5];
    const float* B_re      = ptr[6];
    const float* B_im      = ptr[7];
    const float* C_re      = ptr[8];
    const float* C_im      = ptr[9];
    const float* D         = ptr[10];
    float* out = (float*)d_out;

    static int attr_done = 0;
    if (!attr_done) {
        cudaFuncSetAttribute(k_merged, cudaFuncAttributeMaxDynamicSharedMemorySize, SMEM_BYTES);
        attr_done = 1;
    }

    k_lam<<<1, STATE>>>(nu_log, theta_log, gamma_log);
    int tot = 2 * STATE * IN_DIM + OUT_DIM * STATE;
    k_weights<<<(tot + 255) / 256, 256>>>(B_re, B_im, C_re, C_im);
    k_F<<<dim3(IN_DIM / 16, OUT_DIM / 16), dim3(16, 16)>>>(C_re, C_im, D);

    const long long Y_ELEMS      = (long long)NSEQ * OUT_DIM;   //  8,388,608
    const long long ST_C64_ELEMS = (long long)NSEQ * 2 * STATE; // 33,554,432
    long long cap = (long long)out_size;
    if (cap == Y_ELEMS / 2 + ST_C64_ELEMS / 2) cap *= 2;        // c64-counted case
    long long rem = cap - Y_ELEMS;

    if (rem >= ST_C64_ELEMS) {
        k_merged<<<NY_BLK, 256, SMEM_BYTES>>>(u, x0_re, x0_im, out, cap);
        k_gemm_c64<<<dim3(NSEQ / 128, (2 * STATE) / 64), 256>>>(
            u, IN_DIM, x0_re, x0_im, out + Y_ELEMS, rem);
    } else {
        k_merged<<<NY_BLK + NS_BLK, 256, SMEM_BYTES>>>(u, x0_re, x0_im, out, cap);
    }
}

// round 13
// speedup vs baseline: 2.6111x; 1.1994x over previous
#include <cuda_runtime.h>
#include <cuda_fp16.h>
#include <math.h>
#include <stdint.h>

#define IN_DIM   256
#define STATE    512
#define OUT_DIM  256
#define NSEQ     32768
#define KY       1280   // x0_re(512) | x0_im(512) | u(256)

// ---------------- device scratch (no allocation allowed), 16B-aligned ----------------
__device__ __align__(16) float g_lam_re[STATE];
__device__ __align__(16) float g_lam_im[STATE];
__device__ __align__(16) float g_gam[STATE];
__device__ __align__(16) float g_G[2 * STATE * IN_DIM];  // [1024,256] fp32 (k_F + c64 fallback)
// fp16 weights — ONLY referenced from device code (host shadow address invalid on ATS)
__device__ __align__(16) __half g_Wy_h[OUT_DIM * KY];     // [256][1280] = [P|Q|F]
__device__ __align__(16) __half g_Ws_h[STATE * IN_DIM];   // [512][256]  = Bn_re

// ---------------- PTX helpers (sm_80-era; legal on compute_103) ----------------
__device__ __forceinline__ uint32_t smem_u32(const void* p) {
    uint32_t a;
    asm("{ .reg .u64 t; cvta.to.shared.u64 t, %1; cvt.u32.u64 %0, t; }" : "=r"(a) : "l"(p));
    return a;
}
__device__ __forceinline__ void sts128(uint32_t a, uint32_t x, uint32_t y, uint32_t z, uint32_t w) {
    asm volatile("st.shared.v4.b32 [%0], {%1,%2,%3,%4};" :: "r"(a), "r"(x), "r"(y), "r"(z), "r"(w) : "memory");
}
__device__ __forceinline__ void cp16(uint32_t dst, const void* src) {
    asm volatile("cp.async.cg.shared.global [%0], [%1], 16;" :: "r"(dst), "l"(src) : "memory");
}
__device__ __forceinline__ void cp_commit_wait() {
    asm volatile("cp.async.commit_group;" ::: "memory");
    asm volatile("cp.async.wait_group 0;" ::: "memory");
}
__device__ __forceinline__ void ldm_x4(uint32_t* r, uint32_t addr) {
    asm volatile("ldmatrix.sync.aligned.m8n8.x4.shared.b16 {%0,%1,%2,%3}, [%4];"
        : "=r"(r[0]), "=r"(r[1]), "=r"(r[2]), "=r"(r[3]) : "r"(addr));
}
__device__ __forceinline__ void mma_f16(float* c, const uint32_t* a, const uint32_t* b) {
    asm volatile(
        "mma.sync.aligned.m16n8k16.row.col.f32.f16.f16.f32 "
        "{%0,%1,%2,%3}, {%4,%5,%6,%7}, {%8,%9}, {%0,%1,%2,%3};"
        : "+f"(c[0]), "+f"(c[1]), "+f"(c[2]), "+f"(c[3])
        : "r"(a[0]), "r"(a[1]), "r"(a[2]), "r"(a[3]), "r"(b[0]), "r"(b[1]));
}

// ---------------- precompute (3 launches) ----------------
__global__ void k_lam(const float* __restrict__ nu_log,
                      const float* __restrict__ theta_log,
                      const float* __restrict__ gamma_log) {
    int h = threadIdx.x;
    float mod = expf(-expf(nu_log[h]));
    float th  = expf(theta_log[h]);
    g_lam_re[h] = mod * cosf(th);
    g_lam_im[h] = mod * sinf(th);
    g_gam[h]    = expf(gamma_log[h]);
}

__global__ void k_weights(const float* __restrict__ B_re, const float* __restrict__ B_im,
                          const float* __restrict__ C_re, const float* __restrict__ C_im) {
    int idx = blockIdx.x * blockDim.x + threadIdx.x;
    const int NG = 2 * STATE * IN_DIM;
    const int NP = OUT_DIM * STATE;
    if (idx < NG) {
        int c = idx / IN_DIM, j = idx % IN_DIM, h = c >> 1;
        float b = (c & 1) ? B_im[h * IN_DIM + j] : B_re[h * IN_DIM + j];
        float v = b * g_gam[h];
        g_G[idx] = v;
        if (!(c & 1))
            g_Ws_h[h * IN_DIM + j] = __float2half(v);
    } else if (idx < NG + NP) {
        int t = idx - NG;
        int o = t / STATE, h = t % STATE;
        float cr = C_re[o * STATE + h], ci = C_im[o * STATE + h];
        float lr = g_lam_re[h], li = g_lam_im[h];
        g_Wy_h[o * KY + h]       = __float2half(lr * cr - li * ci);
        g_Wy_h[o * KY + 512 + h] = __float2half(-(li * cr + lr * ci));
    }
}

__global__ void k_F(const float* __restrict__ C_re, const float* __restrict__ C_im,
                    const float* __restrict__ D) {
    __shared__ float sCr[16][16], sCi[16][16], sGr[16][17], sGi[16][17];
    int o0 = blockIdx.y * 16, j0 = blockIdx.x * 16;
    int tx = threadIdx.x, ty = threadIdx.y;
    float acc = 0.f;
    for (int h0 = 0; h0 < STATE; h0 += 16) {
        sCr[ty][tx] = C_re[(o0 + ty) * STATE + h0 + tx];
        sCi[ty][tx] = C_im[(o0 + ty) * STATE + h0 + tx];
        sGr[ty][tx] = g_G[(2 * (h0 + ty)) * IN_DIM + j0 + tx];
        sGi[ty][tx] = g_G[(2 * (h0 + ty) + 1) * IN_DIM + j0 + tx];
        __syncthreads();
#pragma unroll
        for (int k = 0; k < 16; k++)
            acc += sCr[ty][k] * sGr[k][tx] - sCi[ty][k] * sGi[k][tx];
        __syncthreads();
    }
    float fv = D[(o0 + ty) * IN_DIM + j0 + tx] + acc;
    g_Wy_h[(o0 + ty) * KY + 1024 + j0 + tx] = __float2half(fv);
}

// ---------------- merged pipelined mma.sync GEMM (fp16, 2-term A split) ----------------
// BM=128, BN=128, BK=32, 512 thr (16 warps), 1 CTA/SM. N-inner block map (L2 reuse of A).
//   y blocks   [0, 512):    m = t>>1, n = t&1   (K=1280)
//   s blocks   [512, 1536): m = t>>2, n = t&3   (K=256, epilogue Re(lam*x0), clamped)
// Warps: 4 over M x 4 over N, warp tile 32x32 (mt=2, nt=4), 2 MMAs per (mt,nt) per k16.
#define NY_BLK 512
#define NS_BLK 1024
#define A_HI_B 0
#define A_LO_B 10240
#define W_B    20480
#define STG_B  30720
#define SMEM_BYTES (2 * STG_B)   // 61440

__global__ __launch_bounds__(512, 1)
void k_merged(const float* __restrict__ u, const float* __restrict__ x0_re,
              const float* __restrict__ x0_im, float* __restrict__ out, long long lim) {
    extern __shared__ __half sm[];
    uint32_t sb = smem_u32(sm);

    int bid = blockIdx.x;
    bool is_y = bid < NY_BLK;
    int t_ = is_y ? bid : bid - NY_BLK;
    int m0, n0;
    if (is_y) { m0 = (t_ >> 1) * 128; n0 = (t_ & 1) * 128; }
    else      { m0 = (t_ >> 2) * 128; n0 = (t_ & 3) * 128; }
    int KT = is_y ? KY : IN_DIM;
    const __half* __restrict__ Wp = is_y ? g_Wy_h : g_Ws_h;

    int tid  = threadIdx.x;
    int wid  = tid >> 5;
    int lane = tid & 31;
    int wm = wid & 3;          // 4 warps over M (32 rows each)
    int wn = wid >> 2;         // 4 warps over N (32 cols each)

    float acc[2][4][4];
#pragma unroll
    for (int i = 0; i < 2; i++)
#pragma unroll
        for (int j = 0; j < 4; j++)
#pragma unroll
            for (int q = 0; q < 4; q++) acc[i][j][q] = 0.f;

    int lr_ = tid >> 2;         // loader row (0..127) for BOTH A and W
    int lq  = tid & 3;          // k-quarter (8 elems)
    uint32_t lbase = (uint32_t)lr_ * 80 + lq * 16;

    auto a_ptr = [&](int k0) -> const float* {
        const float* Ag; int astr;
        if (is_y) {
            if (k0 < 512)       { Ag = x0_re + k0;          astr = STATE; }
            else if (k0 < 1024) { Ag = x0_im + (k0 - 512);  astr = STATE; }
            else                { Ag = u + (k0 - 1024);     astr = IN_DIM; }
        } else { Ag = u + k0; astr = IN_DIM; }
        return Ag + (size_t)(m0 + lr_) * astr + lq * 8;
    };

    float4 pv0, pv1;            // 8 fp32 A prefetch values per thread
    auto load_a = [&](int k0) {
        const float* p = a_ptr(k0);
        pv0 = *(const float4*)(p);
        pv1 = *(const float4*)(p + 4);
    };
    auto issue_w = [&](int k0, uint32_t stgB) {
        size_t off = (size_t)(n0 + lr_) * KT + k0 + lq * 8;
        cp16(sb + stgB + W_B + lbase, Wp + off);
    };
    auto store_a = [&](uint32_t stgB) {
        float xs[8] = {pv0.x, pv0.y, pv0.z, pv0.w, pv1.x, pv1.y, pv1.z, pv1.w};
        uint32_t hu[4], lu[4];
#pragma unroll
        for (int q = 0; q < 4; q++) {
            __half h0 = __float2half(xs[2 * q]);
            __half h1 = __float2half(xs[2 * q + 1]);
            uint32_t l0 = (uint32_t)__half_as_ushort(__float2half(xs[2 * q]     - __half2float(h0)));
            uint32_t l1 = (uint32_t)__half_as_ushort(__float2half(xs[2 * q + 1] - __half2float(h1)));
            hu[q] = (uint32_t)__half_as_ushort(h0) | ((uint32_t)__half_as_ushort(h1) << 16);
            lu[q] = l0 | (l1 << 16);
        }
        uint32_t b = sb + stgB + lbase;
        sts128(b + A_HI_B, hu[0], hu[1], hu[2], hu[3]);
        sts128(b + A_LO_B, lu[0], lu[1], lu[2], lu[3]);
    };

    // prologue
    load_a(0);
    issue_w(0, 0);
    store_a(0);
    cp_commit_wait();
    __syncthreads();

#pragma unroll 1
    for (int k0 = 0; k0 < KT; k0 += 32) {
        uint32_t cur = (uint32_t)((k0 >> 5) & 1) * STG_B;
        uint32_t nxt = STG_B - cur;
        bool more = (k0 + 32) < KT;
        if (more) { load_a(k0 + 32); issue_w(k0 + 32, nxt); }

        uint32_t sc = sb + cur;
#pragma unroll
        for (int ks = 0; ks < 2; ks++) {
            uint32_t ah[2][4], al[2][4], bh[4][2];
            uint32_t acol = ks * 32 + (lane >> 4) * 16;
#pragma unroll
            for (int mt = 0; mt < 2; mt++) {
                uint32_t r = wm * 32 + mt * 16 + (lane & 15);
                uint32_t ad = r * 80 + acol;
                ldm_x4(ah[mt], sc + A_HI_B + ad);
                ldm_x4(al[mt], sc + A_LO_B + ad);
            }
            // W fragments: paired x4 — one call covers two n-subtiles (16 rows x 16 k)
            uint32_t brow_lo = (uint32_t)((lane >> 4) << 3) + (lane & 7);
            uint32_t bcol    = ks * 32 + ((lane >> 3) & 1) * 16;
#pragma unroll
            for (int p = 0; p < 2; p++) {
                uint32_t n = wn * 32 + p * 16 + brow_lo;
                uint32_t bd = n * 80 + bcol;
                uint32_t th[4];
                ldm_x4(th, sc + W_B + bd);
                bh[2*p][0] = th[0]; bh[2*p][1] = th[1];
                bh[2*p+1][0] = th[2]; bh[2*p+1][1] = th[3];
            }
#pragma unroll
            for (int mt = 0; mt < 2; mt++)
#pragma unroll
                for (int nt = 0; nt < 4; nt++) {
                    mma_f16(acc[mt][nt], ah[mt], bh[nt]);
                    mma_f16(acc[mt][nt], al[mt], bh[nt]);
                }
        }

        if (more) { store_a(nxt); cp_commit_wait(); }
        __syncthreads();
    }

    // epilogue
    int rbase = m0 + wm * 32 + (lane >> 2);
    int cbase = n0 + wn * 32 + 2 * (lane & 3);
#pragma unroll
    for (int mt = 0; mt < 2; mt++) {
#pragma unroll
        for (int nt = 0; nt < 4; nt++) {
            int col = cbase + nt * 8;
#pragma unroll
            for (int hrow = 0; hrow < 2; hrow++) {
                int row = rbase + mt * 16 + hrow * 8;
                float v0 = acc[mt][nt][2 * hrow];
                float v1 = acc[mt][nt][2 * hrow + 1];
                if (is_y) {
                    *(float2*)(out + (size_t)row * OUT_DIM + col) = make_float2(v0, v1);
                } else {
                    long long idx = (long long)NSEQ * OUT_DIM + (long long)row * STATE + col;
                    if (idx + 1 < lim) {
                        float2 lr2 = *(const float2*)&g_lam_re[col];
                        float2 li2 = *(const float2*)&g_lam_im[col];
                        float2 xr  = *(const float2*)&x0_re[(size_t)row * STATE + col];
                        float2 xi  = *(const float2*)&x0_im[(size_t)row * STATE + col];
                        float2 o2;
                        o2.x = lr2.x * xr.x - li2.x * xi.x + v0;
                        o2.y = lr2.y * xr.y - li2.y * xi.y + v1;
                        *(float2*)(out + idx) = o2;
                    }
                }
            }
        }
    }
}

// ---------------- legacy fp32 GEMM (interleaved-c64 state fallback only) ----------------
__global__ __launch_bounds__(256)
void k_gemm_c64(const float* __restrict__ A0, int K0,
                const float* __restrict__ x0_re, const float* __restrict__ x0_im,
                float* __restrict__ out, long long lim) {
    const int BM = 128, BN = 64, BK = 16;
    __shared__ float As[BK][BM + 4];
    __shared__ float Bs[BK][BN + 4];
    int tid = threadIdx.x;
    int m0 = blockIdx.x * BM;
    int n0 = blockIdx.y * BN;
    int tx = tid & 15, ty = tid >> 4;
    float acc[8][4];
#pragma unroll
    for (int i = 0; i < 8; i++)
#pragma unroll
        for (int j = 0; j < 4; j++) acc[i][j] = 0.f;
#pragma unroll 1
    for (int k0 = 0; k0 < K0; k0 += BK) {
#pragma unroll
        for (int l = 0; l < 2; l++) {
            int f = tid + l * 256;
            int r = f >> 2, kk4 = (f & 3) * 4;
            float4 v = *(const float4*)&A0[(size_t)(m0 + r) * K0 + k0 + kk4];
            As[kk4 + 0][r] = v.x; As[kk4 + 1][r] = v.y;
            As[kk4 + 2][r] = v.z; As[kk4 + 3][r] = v.w;
        }
        {
            int n = tid >> 2, kk4 = (tid & 3) * 4;
            float4 v = *(const float4*)&g_G[(size_t)(n0 + n) * K0 + k0 + kk4];
            Bs[kk4 + 0][n] = v.x; Bs[kk4 + 1][n] = v.y;
            Bs[kk4 + 2][n] = v.z; Bs[kk4 + 3][n] = v.w;
        }
        __syncthreads();
#pragma unroll
        for (int kk = 0; kk < BK; kk++) {
            float4 b  = *(const float4*)&Bs[kk][tx * 4];
            float4 a0 = *(const float4*)&As[kk][ty * 8];
            float4 a1 = *(const float4*)&As[kk][ty * 8 + 4];
            float av[8] = {a0.x, a0.y, a0.z, a0.w, a1.x, a1.y, a1.z, a1.w};
            float bv[4] = {b.x, b.y, b.z, b.w};
#pragma unroll
            for (int i = 0; i < 8; i++)
#pragma unroll
                for (int j = 0; j < 4; j++) acc[i][j] += av[i] * bv[j];
        }
        __syncthreads();
    }
    int c0 = n0 + tx * 4;
    int h0 = c0 >> 1;
    float lr0 = g_lam_re[h0],     li0 = g_lam_im[h0];
    float lr1 = g_lam_re[h0 + 1], li1 = g_lam_im[h0 + 1];
#pragma unroll
    for (int i = 0; i < 8; i++) {
        int row = m0 + ty * 8 + i;
        long long idx = (long long)row * (2 * STATE) + c0;
        if (idx + 3 < lim) {
            float xr0 = x0_re[(size_t)row * STATE + h0];
            float xi0 = x0_im[(size_t)row * STATE + h0];
            float xr1 = x0_re[(size_t)row * STATE + h0 + 1];
            float xi1 = x0_im[(size_t)row * STATE + h0 + 1];
            float4 v;
            v.x = lr0 * xr0 - li0 * xi0 + acc[i][0];
            v.y = lr0 * xi0 + li0 * xr0 + acc[i][1];
            v.z = lr1 * xr1 - li1 * xi1 + acc[i][2];
            v.w = lr1 * xi1 + li1 * xr1 + acc[i][3];
            *(float4*)&out[idx] = v;
        }
    }
}

// ---------------- launch ----------------
extern "C" void kernel_launch(void* const* d_in, const int* in_sizes, int n_in,
                              void* d_out, int out_size) {
    const long long expect[11] = {
        (long long)NSEQ * IN_DIM, (long long)NSEQ * STATE, (long long)NSEQ * STATE,
        STATE, STATE, STATE,
        (long long)STATE * IN_DIM, (long long)STATE * IN_DIM,
        (long long)OUT_DIM * STATE, (long long)OUT_DIM * STATE,
        (long long)OUT_DIM * IN_DIM
    };
    const float* ptr[11];
    bool used[32] = {false};
    for (int e = 0; e < 11; e++) {
        ptr[e] = nullptr;
        for (int i = 0; i < n_in; i++) {
            if (!used[i] && (long long)in_sizes[i] == expect[e]) {
                ptr[e] = (const float*)d_in[i];
                used[i] = true;
                break;
            }
        }
        if (!ptr[e]) ptr[e] = (const float*)d_in[e < n_in ? e : 0];
    }
    const float* u         = ptr[0];
    const float* x0_re     = ptr[1];
    const float* x0_im     = ptr[2];
    const float* nu_log    = ptr[3];
    const float* theta_log = ptr[4];
    const float* gamma_log = ptr[5];
    const float* B_re      = ptr[6];
    const float* B_im      = ptr[7];
    const float* C_re      = ptr[8];
    const float* C_im      = ptr[9];
    const float* D         = ptr[10];
    float* out = (float*)d_out;

    static int attr_done = 0;
    if (!attr_done) {
        cudaFuncSetAttribute(k_merged, cudaFuncAttributeMaxDynamicSharedMemorySize, SMEM_BYTES);
        attr_done = 1;
    }

    k_lam<<<1, STATE>>>(nu_log, theta_log, gamma_log);
    int tot = 2 * STATE * IN_DIM + OUT_DIM * STATE;
    k_weights<<<(tot + 255) / 256, 256>>>(B_re, B_im, C_re, C_im);
    k_F<<<dim3(IN_DIM / 16, OUT_DIM / 16), dim3(16, 16)>>>(C_re, C_im, D);

    const long long Y_ELEMS      = (long long)NSEQ * OUT_DIM;   //  8,388,608
    const long long ST_C64_ELEMS = (long long)NSEQ * 2 * STATE; // 33,554,432
    long long cap = (long long)out_size;
    if (cap == Y_ELEMS / 2 + ST_C64_ELEMS / 2) cap *= 2;        // c64-counted case
    long long rem = cap - Y_ELEMS;

    if (rem >= ST_C64_ELEMS) {
        k_merged<<<NY_BLK, 512, SMEM_BYTES>>>(u, x0_re, x0_im, out, cap);
        k_gemm_c64<<<dim3(NSEQ / 128, (2 * STATE) / 64), 256>>>(
            u, IN_DIM, x0_re, x0_im, out + Y_ELEMS, rem);
    } else {
        k_merged<<<NY_BLK + NS_BLK, 512, SMEM_BYTES>>>(u, x0_re, x0_im, out, cap);
    }
}

// round 14
// speedup vs baseline: 2.6304x; 1.0074x over previous
#include <cuda_runtime.h>
#include <cuda_fp16.h>
#include <math.h>
#include <stdint.h>

#define IN_DIM   256
#define STATE    512
#define OUT_DIM  256
#define NSEQ     32768
#define KY       1280   // x0_re(512) | x0_im(512) | u(256)

// ---------------- device scratch (no allocation allowed), 16B-aligned ----------------
__device__ __align__(16) float g_lam_re[STATE];
__device__ __align__(16) float g_lam_im[STATE];
__device__ __align__(16) float g_gam[STATE];
__device__ __align__(16) float g_G[2 * STATE * IN_DIM];  // [1024,256] fp32 (k_F + c64 fallback)
// fp16 weights — ONLY referenced from device code (host shadow address invalid on ATS)
__device__ __align__(16) __half g_Wy_h[OUT_DIM * KY];     // [256][1280] = [P|Q|F]
__device__ __align__(16) __half g_Ws_h[STATE * IN_DIM];   // [512][256]  = Bn_re

// ---------------- PTX helpers (sm_80-era; legal on compute_103) ----------------
__device__ __forceinline__ uint32_t smem_u32(const void* p) {
    uint32_t a;
    asm("{ .reg .u64 t; cvta.to.shared.u64 t, %1; cvt.u32.u64 %0, t; }" : "=r"(a) : "l"(p));
    return a;
}
__device__ __forceinline__ void sts128(uint32_t a, uint32_t x, uint32_t y, uint32_t z, uint32_t w) {
    asm volatile("st.shared.v4.b32 [%0], {%1,%2,%3,%4};" :: "r"(a), "r"(x), "r"(y), "r"(z), "r"(w) : "memory");
}
__device__ __forceinline__ void cp16(uint32_t dst, const void* src) {
    asm volatile("cp.async.cg.shared.global [%0], [%1], 16;" :: "r"(dst), "l"(src) : "memory");
}
__device__ __forceinline__ void cp_commit_wait() {
    asm volatile("cp.async.commit_group;" ::: "memory");
    asm volatile("cp.async.wait_group 0;" ::: "memory");
}
__device__ __forceinline__ void ldm_x4(uint32_t* r, uint32_t addr) {
    asm volatile("ldmatrix.sync.aligned.m8n8.x4.shared.b16 {%0,%1,%2,%3}, [%4];"
        : "=r"(r[0]), "=r"(r[1]), "=r"(r[2]), "=r"(r[3]) : "r"(addr));
}
__device__ __forceinline__ void mma_f16(float* c, const uint32_t* a, const uint32_t* b) {
    asm volatile(
        "mma.sync.aligned.m16n8k16.row.col.f32.f16.f16.f32 "
        "{%0,%1,%2,%3}, {%4,%5,%6,%7}, {%8,%9}, {%0,%1,%2,%3};"
        : "+f"(c[0]), "+f"(c[1]), "+f"(c[2]), "+f"(c[3])
        : "r"(a[0]), "r"(a[1]), "r"(a[2]), "r"(a[3]), "r"(b[0]), "r"(b[1]));
}

// ---------------- precompute (3 launches) ----------------
__global__ void k_lam(const float* __restrict__ nu_log,
                      const float* __restrict__ theta_log,
                      const float* __restrict__ gamma_log) {
    int h = threadIdx.x;
    float mod = expf(-expf(nu_log[h]));
    float th  = expf(theta_log[h]);
    g_lam_re[h] = mod * cosf(th);
    g_lam_im[h] = mod * sinf(th);
    g_gam[h]    = expf(gamma_log[h]);
}

__global__ void k_weights(const float* __restrict__ B_re, const float* __restrict__ B_im,
                          const float* __restrict__ C_re, const float* __restrict__ C_im) {
    int idx = blockIdx.x * blockDim.x + threadIdx.x;
    const int NG = 2 * STATE * IN_DIM;
    const int NP = OUT_DIM * STATE;
    if (idx < NG) {
        int c = idx / IN_DIM, j = idx % IN_DIM, h = c >> 1;
        float b = (c & 1) ? B_im[h * IN_DIM + j] : B_re[h * IN_DIM + j];
        float v = b * g_gam[h];
        g_G[idx] = v;
        if (!(c & 1))
            g_Ws_h[h * IN_DIM + j] = __float2half(v);
    } else if (idx < NG + NP) {
        int t = idx - NG;
        int o = t / STATE, h = t % STATE;
        float cr = C_re[o * STATE + h], ci = C_im[o * STATE + h];
        float lr = g_lam_re[h], li = g_lam_im[h];
        g_Wy_h[o * KY + h]       = __float2half(lr * cr - li * ci);
        g_Wy_h[o * KY + 512 + h] = __float2half(-(li * cr + lr * ci));
    }
}

__global__ void k_F(const float* __restrict__ C_re, const float* __restrict__ C_im,
                    const float* __restrict__ D) {
    __shared__ float sCr[16][16], sCi[16][16], sGr[16][17], sGi[16][17];
    int o0 = blockIdx.y * 16, j0 = blockIdx.x * 16;
    int tx = threadIdx.x, ty = threadIdx.y;
    float acc = 0.f;
    for (int h0 = 0; h0 < STATE; h0 += 16) {
        sCr[ty][tx] = C_re[(o0 + ty) * STATE + h0 + tx];
        sCi[ty][tx] = C_im[(o0 + ty) * STATE + h0 + tx];
        sGr[ty][tx] = g_G[(2 * (h0 + ty)) * IN_DIM + j0 + tx];
        sGi[ty][tx] = g_G[(2 * (h0 + ty) + 1) * IN_DIM + j0 + tx];
        __syncthreads();
#pragma unroll
        for (int k = 0; k < 16; k++)
            acc += sCr[ty][k] * sGr[k][tx] - sCi[ty][k] * sGi[k][tx];
        __syncthreads();
    }
    float fv = D[(o0 + ty) * IN_DIM + j0 + tx] + acc;
    g_Wy_h[(o0 + ty) * KY + 1024 + j0 + tx] = __float2half(fv);
}

// ---------------- merged pipelined mma.sync GEMM (fp16, 2-term A split) ----------------
// BM=128, BN=128, BK=32, 512 thr (16 warps), 1 CTA/SM. N-inner block map (L2 reuse of A).
//   y blocks   [0, 512):    m = t>>1, n = t&1   (K=1280)
//   s blocks   [512, 1536): m = t>>2, n = t&3   (K=256, epilogue Re(lam*x0), clamped)
// Warps: 4 over M x 4 over N, warp tile 32x32 (mt=2, nt=4), 2 MMAs per (mt,nt) per k16.
#define NY_BLK 512
#define NS_BLK 1024
#define A_HI_B 0
#define A_LO_B 10240
#define W_B    20480
#define STG_B  30720
#define SMEM_BYTES (2 * STG_B)   // 61440

__global__ __launch_bounds__(512, 1)
void k_merged(const float* __restrict__ u, const float* __restrict__ x0_re,
              const float* __restrict__ x0_im, float* __restrict__ out, long long lim) {
    extern __shared__ __half sm[];
    uint32_t sb = smem_u32(sm);

    int bid = blockIdx.x;
    bool is_y = bid < NY_BLK;
    int t_ = is_y ? bid : bid - NY_BLK;
    int m0, n0;
    if (is_y) { m0 = (t_ >> 1) * 128; n0 = (t_ & 1) * 128; }
    else      { m0 = (t_ >> 2) * 128; n0 = (t_ & 3) * 128; }
    int KT = is_y ? KY : IN_DIM;
    const __half* __restrict__ Wp = is_y ? g_Wy_h : g_Ws_h;

    int tid  = threadIdx.x;
    int wid  = tid >> 5;
    int lane = tid & 31;
    int wm = wid & 3;          // 4 warps over M (32 rows each)
    int wn = wid >> 2;         // 4 warps over N (32 cols each)

    float acc[2][4][4];
#pragma unroll
    for (int i = 0; i < 2; i++)
#pragma unroll
        for (int j = 0; j < 4; j++)
#pragma unroll
            for (int q = 0; q < 4; q++) acc[i][j][q] = 0.f;

    int lr_ = tid >> 2;         // loader row (0..127) for BOTH A and W
    int lq  = tid & 3;          // k-quarter (8 elems)
    uint32_t lbase = (uint32_t)lr_ * 80 + lq * 16;

    auto a_ptr = [&](int k0) -> const float* {
        const float* Ag; int astr;
        if (is_y) {
            if (k0 < 512)       { Ag = x0_re + k0;          astr = STATE; }
            else if (k0 < 1024) { Ag = x0_im + (k0 - 512);  astr = STATE; }
            else                { Ag = u + (k0 - 1024);     astr = IN_DIM; }
        } else { Ag = u + k0; astr = IN_DIM; }
        return Ag + (size_t)(m0 + lr_) * astr + lq * 8;
    };

    float4 pv0, pv1;            // 8 fp32 A prefetch values per thread
    auto load_a = [&](int k0) {
        const float* p = a_ptr(k0);
        pv0 = *(const float4*)(p);
        pv1 = *(const float4*)(p + 4);
    };
    auto issue_w = [&](int k0, uint32_t stgB) {
        size_t off = (size_t)(n0 + lr_) * KT + k0 + lq * 8;
        cp16(sb + stgB + W_B + lbase, Wp + off);
    };
    auto store_a = [&](uint32_t stgB) {
        float xs[8] = {pv0.x, pv0.y, pv0.z, pv0.w, pv1.x, pv1.y, pv1.z, pv1.w};
        uint32_t hu[4], lu[4];
#pragma unroll
        for (int q = 0; q < 4; q++) {
            __half h0 = __float2half(xs[2 * q]);
            __half h1 = __float2half(xs[2 * q + 1]);
            uint32_t l0 = (uint32_t)__half_as_ushort(__float2half(xs[2 * q]     - __half2float(h0)));
            uint32_t l1 = (uint32_t)__half_as_ushort(__float2half(xs[2 * q + 1] - __half2float(h1)));
            hu[q] = (uint32_t)__half_as_ushort(h0) | ((uint32_t)__half_as_ushort(h1) << 16);
            lu[q] = l0 | (l1 << 16);
        }
        uint32_t b = sb + stgB + lbase;
        sts128(b + A_HI_B, hu[0], hu[1], hu[2], hu[3]);
        sts128(b + A_LO_B, lu[0], lu[1], lu[2], lu[3]);
    };

    // prologue
    load_a(0);
    issue_w(0, 0);
    store_a(0);
    cp_commit_wait();
    __syncthreads();

#pragma unroll 1
    for (int k0 = 0; k0 < KT; k0 += 32) {
        uint32_t cur = (uint32_t)((k0 >> 5) & 1) * STG_B;
        uint32_t nxt = STG_B - cur;
        bool more = (k0 + 32) < KT;
        if (more) { load_a(k0 + 32); issue_w(k0 + 32, nxt); }

        uint32_t sc = sb + cur;
#pragma unroll
        for (int ks = 0; ks < 2; ks++) {
            uint32_t ah[2][4], al[2][4], bh[4][2];
            uint32_t acol = ks * 32 + (lane >> 4) * 16;
#pragma unroll
            for (int mt = 0; mt < 2; mt++) {
                uint32_t r = wm * 32 + mt * 16 + (lane & 15);
                uint32_t ad = r * 80 + acol;
                ldm_x4(ah[mt], sc + A_HI_B + ad);
                ldm_x4(al[mt], sc + A_LO_B + ad);
            }
            // W fragments: paired x4 — one call covers two n-subtiles (16 rows x 16 k)
            uint32_t brow_lo = (uint32_t)((lane >> 4) << 3) + (lane & 7);
            uint32_t bcol    = ks * 32 + ((lane >> 3) & 1) * 16;
#pragma unroll
            for (int p = 0; p < 2; p++) {
                uint32_t n = wn * 32 + p * 16 + brow_lo;
                uint32_t bd = n * 80 + bcol;
                uint32_t th[4];
                ldm_x4(th, sc + W_B + bd);
                bh[2*p][0] = th[0]; bh[2*p][1] = th[1];
                bh[2*p+1][0] = th[2]; bh[2*p+1][1] = th[3];
            }
#pragma unroll
            for (int mt = 0; mt < 2; mt++)
#pragma unroll
                for (int nt = 0; nt < 4; nt++) {
                    mma_f16(acc[mt][nt], ah[mt], bh[nt]);
                    mma_f16(acc[mt][nt], al[mt], bh[nt]);
                }
        }

        if (more) { store_a(nxt); cp_commit_wait(); }
        __syncthreads();
    }

    // epilogue
    int rbase = m0 + wm * 32 + (lane >> 2);
    int cbase = n0 + wn * 32 + 2 * (lane & 3);
#pragma unroll
    for (int mt = 0; mt < 2; mt++) {
#pragma unroll
        for (int nt = 0; nt < 4; nt++) {
            int col = cbase + nt * 8;
#pragma unroll
            for (int hrow = 0; hrow < 2; hrow++) {
                int row = rbase + mt * 16 + hrow * 8;
                float v0 = acc[mt][nt][2 * hrow];
                float v1 = acc[mt][nt][2 * hrow + 1];
                if (is_y) {
                    *(float2*)(out + (size_t)row * OUT_DIM + col) = make_float2(v0, v1);
                } else {
                    long long idx = (long long)NSEQ * OUT_DIM + (long long)row * STATE + col;
                    if (idx + 1 < lim) {
                        float2 lr2 = *(const float2*)&g_lam_re[col];
                        float2 li2 = *(const float2*)&g_lam_im[col];
                        float2 xr  = *(const float2*)&x0_re[(size_t)row * STATE + col];
                        float2 xi  = *(const float2*)&x0_im[(size_t)row * STATE + col];
                        float2 o2;
                        o2.x = lr2.x * xr.x - li2.x * xi.x + v0;
                        o2.y = lr2.y * xr.y - li2.y * xi.y + v1;
                        *(float2*)(out + idx) = o2;
                    }
                }
            }
        }
    }
}

// ---------------- legacy fp32 GEMM (interleaved-c64 state fallback only) ----------------
__global__ __launch_bounds__(256)
void k_gemm_c64(const float* __restrict__ A0, int K0,
                const float* __restrict__ x0_re, const float* __restrict__ x0_im,
                float* __restrict__ out, long long lim) {
    const int BM = 128, BN = 64, BK = 16;
    __shared__ float As[BK][BM + 4];
    __shared__ float Bs[BK][BN + 4];
    int tid = threadIdx.x;
    int m0 = blockIdx.x * BM;
    int n0 = blockIdx.y * BN;
    int tx = tid & 15, ty = tid >> 4;
    float acc[8][4];
#pragma unroll
    for (int i = 0; i < 8; i++)
#pragma unroll
        for (int j = 0; j < 4; j++) acc[i][j] = 0.f;
#pragma unroll 1
    for (int k0 = 0; k0 < K0; k0 += BK) {
#pragma unroll
        for (int l = 0; l < 2; l++) {
            int f = tid + l * 256;
            int r = f >> 2, kk4 = (f & 3) * 4;
            float4 v = *(const float4*)&A0[(size_t)(m0 + r) * K0 + k0 + kk4];
            As[kk4 + 0][r] = v.x; As[kk4 + 1][r] = v.y;
            As[kk4 + 2][r] = v.z; As[kk4 + 3][r] = v.w;
        }
        {
            int n = tid >> 2, kk4 = (tid & 3) * 4;
            float4 v = *(const float4*)&g_G[(size_t)(n0 + n) * K0 + k0 + kk4];
            Bs[kk4 + 0][n] = v.x; Bs[kk4 + 1][n] = v.y;
            Bs[kk4 + 2][n] = v.z; Bs[kk4 + 3][n] = v.w;
        }
        __syncthreads();
#pragma unroll
        for (int kk = 0; kk < BK; kk++) {
            float4 b  = *(const float4*)&Bs[kk][tx * 4];
            float4 a0 = *(const float4*)&As[kk][ty * 8];
            float4 a1 = *(const float4*)&As[kk][ty * 8 + 4];
            float av[8] = {a0.x, a0.y, a0.z, a0.w, a1.x, a1.y, a1.z, a1.w};
            float bv[4] = {b.x, b.y, b.z, b.w};
#pragma unroll
            for (int i = 0; i < 8; i++)
#pragma unroll
                for (int j = 0; j < 4; j++) acc[i][j] += av[i] * bv[j];
        }
        __syncthreads();
    }
    int c0 = n0 + tx * 4;
    int h0 = c0 >> 1;
    float lr0 = g_lam_re[h0],     li0 = g_lam_im[h0];
    float lr1 = g_lam_re[h0 + 1], li1 = g_lam_im[h0 + 1];
#pragma unroll
    for (int i = 0; i < 8; i++) {
        int row = m0 + ty * 8 + i;
        long long idx = (long long)row * (2 * STATE) + c0;
        if (idx + 3 < lim) {
            float xr0 = x0_re[(size_t)row * STATE + h0];
            float xi0 = x0_im[(size_t)row * STATE + h0];
            float xr1 = x0_re[(size_t)row * STATE + h0 + 1];
            float xi1 = x0_im[(size_t)row * STATE + h0 + 1];
            float4 v;
            v.x = lr0 * xr0 - li0 * xi0 + acc[i][0];
            v.y = lr0 * xi0 + li0 * xr0 + acc[i][1];
            v.z = lr1 * xr1 - li1 * xi1 + acc[i][2];
            v.w = lr1 * xi1 + li1 * xr1 + acc[i][3];
            *(float4*)&out[idx] = v;
        }
    }
}

// ---------------- launch ----------------
extern "C" void kernel_launch(void* const* d_in, const int* in_sizes, int n_in,
                              void* d_out, int out_size) {
    const long long expect[11] = {
        (long long)NSEQ * IN_DIM, (long long)NSEQ * STATE, (long long)NSEQ * STATE,
        STATE, STATE, STATE,
        (long long)STATE * IN_DIM, (long long)STATE * IN_DIM,
        (long long)OUT_DIM * STATE, (long long)OUT_DIM * STATE,
        (long long)OUT_DIM * IN_DIM
    };
    const float* ptr[11];
    bool used[32] = {false};
    for (int e = 0; e < 11; e++) {
        ptr[e] = nullptr;
        for (int i = 0; i < n_in; i++) {
            if (!used[i] && (long long)in_sizes[i] == expect[e]) {
                ptr[e] = (const float*)d_in[i];
                used[i] = true;
                break;
            }
        }
        if (!ptr[e]) ptr[e] = (const float*)d_in[e < n_in ? e : 0];
    }
    const float* u         = ptr[0];
    const float* x0_re     = ptr[1];
    const float* x0_im     = ptr[2];
    const float* nu_log    = ptr[3];
    const float* theta_log = ptr[4];
    const float* gamma_log = ptr[5];
    const float* B_re      = ptr[6];
    const float* B_im      = ptr[7];
    const float* C_re      = ptr[8];
    const float* C_im      = ptr[9];
    const float* D         = ptr[10];
    float* out = (float*)d_out;

    static int attr_done = 0;
    if (!attr_done) {
        cudaFuncSetAttribute(k_merged, cudaFuncAttributeMaxDynamicSharedMemorySize, SMEM_BYTES);
        attr_done = 1;
    }

    k_lam<<<1, STATE>>>(nu_log, theta_log, gamma_log);
    int tot = 2 * STATE * IN_DIM + OUT_DIM * STATE;
    k_weights<<<(tot + 255) / 256, 256>>>(B_re, B_im, C_re, C_im);
    k_F<<<dim3(IN_DIM / 16, OUT_DIM / 16), dim3(16, 16)>>>(C_re, C_im, D);

    const long long Y_ELEMS      = (long long)NSEQ * OUT_DIM;   //  8,388,608
    const long long ST_C64_ELEMS = (long long)NSEQ * 2 * STATE; // 33,554,432
    long long cap = (long long)out_size;
    if (cap == Y_ELEMS / 2 + ST_C64_ELEMS / 2) cap *= 2;        // c64-counted case
    long long rem = cap - Y_ELEMS;

    if (rem >= ST_C64_ELEMS) {
        k_merged<<<NY_BLK, 512, SMEM_BYTES>>>(u, x0_re, x0_im, out, cap);
        k_gemm_c64<<<dim3(NSEQ / 128, (2 * STATE) / 64), 256>>>(
            u, IN_DIM, x0_re, x0_im, out + Y_ELEMS, rem);
    } else {
        k_merged<<<NY_BLK + NS_BLK, 512, SMEM_BYTES>>>(u, x0_re, x0_im, out, cap);
    }
}